// round 1
// baseline (speedup 1.0000x reference)
#include <cuda_runtime.h>
#include <cuda_bf16.h>
#include <math_constants.h>

// Problem constants
#define BB   2
#define NN   4096
#define MM   4096
#define DD   512
#define HH   8
#define PP   64          // head dim
#define RR   (BB * NN)   // 8192 rows for projections

// ---------------- scratch (allocation-free: __device__ globals) ----------------
__device__ float g_q[(size_t)BB * NN * DD];
__device__ float g_k[(size_t)BB * MM * DD];
__device__ float g_v[(size_t)BB * MM * DD];

// ---------------- Projection GEMM: Y[R,512] = X[R,512] @ W[512,512] + b ----------------
// 128x128 block tile, BK=16, 256 threads, 8x8 micro-tile per thread.
#define BM 128
#define BN 128
#define BK 16

__global__ __launch_bounds__(256) void gemm_bias_kernel(
    const float* __restrict__ X, const float* __restrict__ W,
    const float* __restrict__ bias, float* __restrict__ Y)
{
    __shared__ float As[BK][BM];   // transposed: As[k][m]
    __shared__ float Bs[BK][BN];   // Bs[k][n]

    const int tid = threadIdx.x;
    const int cb  = blockIdx.x * BN;   // output col base
    const int rb  = blockIdx.y * BM;   // output row base

    const int tr = tid / 16;   // 0..15
    const int tc = tid % 16;   // 0..15

    float acc[8][8];
#pragma unroll
    for (int i = 0; i < 8; i++)
#pragma unroll
        for (int j = 0; j < 8; j++) acc[i][j] = 0.0f;

    for (int k0 = 0; k0 < DD; k0 += BK) {
        // Load A tile: X[rb + r][k0 + c], r in [0,128), c in [0,16).
        // 512 float4 loads; each thread does 2. Store transposed into As.
#pragma unroll
        for (int t = 0; t < 2; t++) {
            int idx = tid * 2 + t;              // 0..511
            int r   = idx / 4;                  // 0..127
            int c4  = idx % 4;                  // 0..3  (float4 along k)
            float4 v = *(const float4*)(X + (size_t)(rb + r) * DD + k0 + c4 * 4);
            As[c4 * 4 + 0][r] = v.x;
            As[c4 * 4 + 1][r] = v.y;
            As[c4 * 4 + 2][r] = v.z;
            As[c4 * 4 + 3][r] = v.w;
        }
        // Load B tile: W[k0 + r][cb + c], r in [0,16), c in [0,128).
#pragma unroll
        for (int t = 0; t < 2; t++) {
            int idx = tid * 2 + t;              // 0..511
            int r   = idx / 32;                 // 0..15
            int c4  = idx % 32;                 // 0..31
            float4 v = *(const float4*)(W + (size_t)(k0 + r) * DD + cb + c4 * 4);
            *(float4*)&Bs[r][c4 * 4] = v;
        }
        __syncthreads();

#pragma unroll
        for (int k = 0; k < BK; k++) {
            float a[8], b[8];
#pragma unroll
            for (int i = 0; i < 8; i++) a[i] = As[k][tr * 8 + i];
#pragma unroll
            for (int j = 0; j < 8; j++) b[j] = Bs[k][tc * 8 + j];
#pragma unroll
            for (int i = 0; i < 8; i++)
#pragma unroll
                for (int j = 0; j < 8; j++)
                    acc[i][j] = fmaf(a[i], b[j], acc[i][j]);
        }
        __syncthreads();
    }

    // Epilogue: add bias, store.
#pragma unroll
    for (int i = 0; i < 8; i++) {
        int row = rb + tr * 8 + i;
#pragma unroll
        for (int j = 0; j < 8; j += 4) {
            int col = cb + tc * 8 + j;
            float4 o;
            o.x = acc[i][j + 0] + bias[col + 0];
            o.y = acc[i][j + 1] + bias[col + 1];
            o.z = acc[i][j + 2] + bias[col + 2];
            o.w = acc[i][j + 3] + bias[col + 3];
            *(float4*)(Y + (size_t)row * DD + col) = o;
        }
    }
}

// ---------------- Flash attention (fp32 baseline) ----------------
// One thread = one query row. Block = 128 query rows of one (b,h).
// K/V tiles of 32 rows x 64 dims in smem; scores kept in registers.
#define BQ  128
#define BKV 32

__global__ __launch_bounds__(BQ) void attn_kernel(
    const float* __restrict__ Q, const float* __restrict__ K,
    const float* __restrict__ V, float* __restrict__ O)
{
    __shared__ float Ks[BKV][PP];
    __shared__ float Vs[BKV][PP];

    const int b = blockIdx.z;
    const int h = blockIdx.y;
    const int qrow = blockIdx.x * BQ + threadIdx.x;   // query index in [0, NN)

    const float* qptr = Q + ((size_t)(b * NN + qrow)) * DD + h * PP;
    const float* Kb   = K + ((size_t)b * MM) * DD + h * PP;
    const float* Vb   = V + ((size_t)b * MM) * DD + h * PP;

    float q[PP];
#pragma unroll
    for (int d = 0; d < PP; d += 4) {
        float4 t = *(const float4*)(qptr + d);
        q[d] = t.x; q[d + 1] = t.y; q[d + 2] = t.z; q[d + 3] = t.w;
    }

    float acc[PP];
#pragma unroll
    for (int d = 0; d < PP; d++) acc[d] = 0.0f;
    float m = -CUDART_INF_F;
    float l = 0.0f;

    const float scale = 0.125f;   // 1/sqrt(64)

    for (int kt = 0; kt < MM; kt += BKV) {
        __syncthreads();   // protect previous tile reads
        // Load K/V tiles: 32x64 floats each = 512 float4 per matrix; 128 threads -> 4 each.
        for (int i = threadIdx.x; i < BKV * 16; i += BQ) {
            int r  = i / 16;
            int c4 = (i % 16) * 4;
            *(float4*)&Ks[r][c4] = *(const float4*)(Kb + (size_t)(kt + r) * DD + c4);
            *(float4*)&Vs[r][c4] = *(const float4*)(Vb + (size_t)(kt + r) * DD + c4);
        }
        __syncthreads();

        // Scores for this tile (registers).
        float s[BKV];
#pragma unroll
        for (int j = 0; j < BKV; j++) {
            float a0 = 0.0f, a1 = 0.0f, a2 = 0.0f, a3 = 0.0f;
#pragma unroll
            for (int d = 0; d < PP; d += 4) {
                float4 kv = *(const float4*)&Ks[j][d];
                a0 = fmaf(q[d],     kv.x, a0);
                a1 = fmaf(q[d + 1], kv.y, a1);
                a2 = fmaf(q[d + 2], kv.z, a2);
                a3 = fmaf(q[d + 3], kv.w, a3);
            }
            s[j] = ((a0 + a1) + (a2 + a3)) * scale;
        }

        // Online softmax update.
        float mt = m;
#pragma unroll
        for (int j = 0; j < BKV; j++) mt = fmaxf(mt, s[j]);
        float corr = __expf(m - mt);   // 0 on first tile (m = -inf)
        m = mt;
        l *= corr;
#pragma unroll
        for (int d = 0; d < PP; d++) acc[d] *= corr;

#pragma unroll
        for (int j = 0; j < BKV; j++) {
            float p = __expf(s[j] - m);
            l += p;
#pragma unroll
            for (int d = 0; d < PP; d += 4) {
                float4 vv = *(const float4*)&Vs[j][d];
                acc[d]     = fmaf(p, vv.x, acc[d]);
                acc[d + 1] = fmaf(p, vv.y, acc[d + 1]);
                acc[d + 2] = fmaf(p, vv.z, acc[d + 2]);
                acc[d + 3] = fmaf(p, vv.w, acc[d + 3]);
            }
        }
    }

    const float inv = 1.0f / l;
    float* optr = O + ((size_t)(b * NN + qrow)) * DD + h * PP;
#pragma unroll
    for (int d = 0; d < PP; d += 4) {
        float4 o;
        o.x = acc[d] * inv; o.y = acc[d + 1] * inv;
        o.z = acc[d + 2] * inv; o.w = acc[d + 3] * inv;
        *(float4*)(optr + d) = o;
    }
}

// ---------------- launch ----------------
extern "C" void kernel_launch(void* const* d_in, const int* in_sizes, int n_in,
                              void* d_out, int out_size)
{
    const float* queries = (const float*)d_in[0];
    const float* keys    = (const float*)d_in[1];
    const float* values  = (const float*)d_in[2];
    const float* Wq      = (const float*)d_in[3];
    const float* bq      = (const float*)d_in[4];
    const float* Wk      = (const float*)d_in[5];
    const float* bk      = (const float*)d_in[6];
    const float* Wv      = (const float*)d_in[7];
    const float* bv      = (const float*)d_in[8];
    float* out = (float*)d_out;

    float *pq, *pk, *pv;
    cudaGetSymbolAddress((void**)&pq, g_q);
    cudaGetSymbolAddress((void**)&pk, g_k);
    cudaGetSymbolAddress((void**)&pv, g_v);

    dim3 gGrid(DD / BN, RR / BM);      // (4, 64)
    gemm_bias_kernel<<<gGrid, 256>>>(queries, Wq, bq, pq);
    gemm_bias_kernel<<<gGrid, 256>>>(keys,    Wk, bk, pk);
    gemm_bias_kernel<<<gGrid, 256>>>(values,  Wv, bv, pv);

    dim3 aGrid(NN / BQ, HH, BB);       // (32, 8, 2)
    attn_kernel<<<aGrid, BQ>>>(pq, pk, pv, out);
}

// round 2
// speedup vs baseline: 1.1657x; 1.1657x over previous
#include <cuda_runtime.h>
#include <cuda_bf16.h>
#include <math_constants.h>

// Problem constants
#define BB   2
#define NN   4096
#define MM   4096
#define DD   512
#define HH   8
#define PP   64          // head dim
#define RR   (BB * NN)   // 8192 rows for projections

// ---------------- scratch (allocation-free: __device__ globals) ----------------
__device__ float g_q[(size_t)BB * NN * DD];
__device__ float g_k[(size_t)BB * MM * DD];
__device__ float g_v[(size_t)BB * MM * DD];

// ---------------- Projection GEMM: Y[R,512] = X[R,512] @ W[512,512] + b ----------------
#define BM 128
#define BN 128
#define BK 16

__global__ __launch_bounds__(256) void gemm_bias_kernel(
    const float* __restrict__ X, const float* __restrict__ W,
    const float* __restrict__ bias, float* __restrict__ Y)
{
    __shared__ float As[BK][BM];   // transposed: As[k][m]
    __shared__ float Bs[BK][BN];   // Bs[k][n]

    const int tid = threadIdx.x;
    const int cb  = blockIdx.x * BN;
    const int rb  = blockIdx.y * BM;

    const int tr = tid / 16;
    const int tc = tid % 16;

    float acc[8][8];
#pragma unroll
    for (int i = 0; i < 8; i++)
#pragma unroll
        for (int j = 0; j < 8; j++) acc[i][j] = 0.0f;

    for (int k0 = 0; k0 < DD; k0 += BK) {
#pragma unroll
        for (int t = 0; t < 2; t++) {
            int idx = tid * 2 + t;
            int r   = idx / 4;
            int c4  = idx % 4;
            float4 v = *(const float4*)(X + (size_t)(rb + r) * DD + k0 + c4 * 4);
            As[c4 * 4 + 0][r] = v.x;
            As[c4 * 4 + 1][r] = v.y;
            As[c4 * 4 + 2][r] = v.z;
            As[c4 * 4 + 3][r] = v.w;
        }
#pragma unroll
        for (int t = 0; t < 2; t++) {
            int idx = tid * 2 + t;
            int r   = idx / 32;
            int c4  = idx % 32;
            float4 v = *(const float4*)(W + (size_t)(k0 + r) * DD + cb + c4 * 4);
            *(float4*)&Bs[r][c4 * 4] = v;
        }
        __syncthreads();

#pragma unroll
        for (int k = 0; k < BK; k++) {
            float a[8], b[8];
#pragma unroll
            for (int i = 0; i < 8; i++) a[i] = As[k][tr * 8 + i];
#pragma unroll
            for (int j = 0; j < 8; j++) b[j] = Bs[k][tc * 8 + j];
#pragma unroll
            for (int i = 0; i < 8; i++)
#pragma unroll
                for (int j = 0; j < 8; j++)
                    acc[i][j] = fmaf(a[i], b[j], acc[i][j]);
        }
        __syncthreads();
    }

#pragma unroll
    for (int i = 0; i < 8; i++) {
        int row = rb + tr * 8 + i;
#pragma unroll
        for (int j = 0; j < 8; j += 4) {
            int col = cb + tc * 8 + j;
            float4 o;
            o.x = acc[i][j + 0] + bias[col + 0];
            o.y = acc[i][j + 1] + bias[col + 1];
            o.z = acc[i][j + 2] + bias[col + 2];
            o.w = acc[i][j + 3] + bias[col + 3];
            *(float4*)(Y + (size_t)row * DD + col) = o;
        }
    }
}

// ---------------- Flash attention, register-tiled (fp32) ----------------
// CTA: 128 threads, 128 query rows of one (b,h). KV tile = 64 keys.
// Thread grid 16(tr) x 8(tc). Each thread owns 8 query rows (tr*8+i) in
// BOTH the QK and PV GEMMs, so softmax state (m, l) stays in registers.
//   QK: S[q][k] micro 8x8, contraction over d; Q stored d-major, K stored d-major.
//   PV: O[q][d] micro 8x8, contraction over k; P staged through smem k-major.
#define BQ   128
#define KT   64
#define QS_STRIDE 136   // Qs[d][q], padded
#define KS_STRIDE 72    // Ks[d][k], padded
#define VS_STRIDE 72    // Vs[k][d], padded
#define PS_STRIDE 136   // Ps[k][q], padded

#define SMEM_QS 0
#define SMEM_KS (PP * QS_STRIDE)
#define SMEM_VS (SMEM_KS + PP * KS_STRIDE)
#define SMEM_PS (SMEM_VS + KT * VS_STRIDE)
#define ATTN_SMEM_FLOATS (SMEM_PS + KT * PS_STRIDE)

__global__ __launch_bounds__(128) void attn_kernel(
    const float* __restrict__ Q, const float* __restrict__ K,
    const float* __restrict__ V, float* __restrict__ O)
{
    extern __shared__ float sm[];
    float* sQs = sm + SMEM_QS;
    float* sKs = sm + SMEM_KS;
    float* sVs = sm + SMEM_VS;
    float* sPs = sm + SMEM_PS;

    const int tid = threadIdx.x;
    const int tr  = tid >> 3;       // 0..15 -> query rows tr*8..tr*8+7
    const int tc  = tid & 7;        // 0..7  -> key cols / out dims tc*8..tc*8+7

    const int b  = blockIdx.z;
    const int h  = blockIdx.y;
    const int q0 = blockIdx.x * BQ;

    const float* Qb = Q + ((size_t)(b * NN + q0)) * DD + h * PP;
    const float* Kb = K + ((size_t)b * MM) * DD + h * PP;
    const float* Vb = V + ((size_t)b * MM) * DD + h * PP;

    // Load Q tile transposed (d-major), pre-scaled by 1/sqrt(P).
    for (int it = tid; it < BQ * (PP / 4); it += 128) {
        int r  = it >> 4;           // query row 0..127
        int c4 = it & 15;           // float4 index along d
        float4 v = *(const float4*)(Qb + (size_t)r * DD + c4 * 4);
        sQs[(c4 * 4 + 0) * QS_STRIDE + r] = v.x * 0.125f;
        sQs[(c4 * 4 + 1) * QS_STRIDE + r] = v.y * 0.125f;
        sQs[(c4 * 4 + 2) * QS_STRIDE + r] = v.z * 0.125f;
        sQs[(c4 * 4 + 3) * QS_STRIDE + r] = v.w * 0.125f;
    }

    float acc[8][8];
#pragma unroll
    for (int i = 0; i < 8; i++)
#pragma unroll
        for (int j = 0; j < 8; j++) acc[i][j] = 0.0f;
    float mrow[8], lrow[8];
#pragma unroll
    for (int i = 0; i < 8; i++) { mrow[i] = -CUDART_INF_F; lrow[i] = 0.0f; }

    for (int kt = 0; kt < MM; kt += KT) {
        __syncthreads();   // previous tile fully consumed
        // Load K (transposed to d-major) and V (natural) tiles.
        for (int it = tid; it < KT * (PP / 4); it += 128) {
            int r  = it >> 4;       // key row 0..63
            int c4 = it & 15;
            float4 kv = *(const float4*)(Kb + (size_t)(kt + r) * DD + c4 * 4);
            sKs[(c4 * 4 + 0) * KS_STRIDE + r] = kv.x;
            sKs[(c4 * 4 + 1) * KS_STRIDE + r] = kv.y;
            sKs[(c4 * 4 + 2) * KS_STRIDE + r] = kv.z;
            sKs[(c4 * 4 + 3) * KS_STRIDE + r] = kv.w;
            float4 vv = *(const float4*)(Vb + (size_t)(kt + r) * DD + c4 * 4);
            *(float4*)&sVs[r * VS_STRIDE + c4 * 4] = vv;
        }
        __syncthreads();

        // --- QK^T: S micro 8x8, contraction over d ---
        float s[8][8];
#pragma unroll
        for (int i = 0; i < 8; i++)
#pragma unroll
            for (int j = 0; j < 8; j++) s[i][j] = 0.0f;

#pragma unroll 4
        for (int d = 0; d < PP; d++) {
            float4 a0 = *(const float4*)&sQs[d * QS_STRIDE + tr * 8];
            float4 a1 = *(const float4*)&sQs[d * QS_STRIDE + tr * 8 + 4];
            float4 b0 = *(const float4*)&sKs[d * KS_STRIDE + tc * 8];
            float4 b1 = *(const float4*)&sKs[d * KS_STRIDE + tc * 8 + 4];
            float a[8] = {a0.x, a0.y, a0.z, a0.w, a1.x, a1.y, a1.z, a1.w};
            float bq_[8] = {b0.x, b0.y, b0.z, b0.w, b1.x, b1.y, b1.z, b1.w};
#pragma unroll
            for (int i = 0; i < 8; i++)
#pragma unroll
                for (int j = 0; j < 8; j++)
                    s[i][j] = fmaf(a[i], bq_[j], s[i][j]);
        }

        // --- Online softmax (rows owned by this thread; reduce over tc group) ---
#pragma unroll
        for (int i = 0; i < 8; i++) {
            float mx = s[i][0];
#pragma unroll
            for (int j = 1; j < 8; j++) mx = fmaxf(mx, s[i][j]);
            mx = fmaxf(mx, __shfl_xor_sync(0xffffffffu, mx, 1));
            mx = fmaxf(mx, __shfl_xor_sync(0xffffffffu, mx, 2));
            mx = fmaxf(mx, __shfl_xor_sync(0xffffffffu, mx, 4));
            float mn = fmaxf(mrow[i], mx);
            float corr = __expf(mrow[i] - mn);
            mrow[i] = mn;
            float ls = 0.0f;
#pragma unroll
            for (int j = 0; j < 8; j++) {
                float p = __expf(s[i][j] - mn);
                s[i][j] = p;
                ls += p;
            }
            ls += __shfl_xor_sync(0xffffffffu, ls, 1);
            ls += __shfl_xor_sync(0xffffffffu, ls, 2);
            ls += __shfl_xor_sync(0xffffffffu, ls, 4);
            lrow[i] = lrow[i] * corr + ls;
#pragma unroll
            for (int j = 0; j < 8; j++) acc[i][j] *= corr;
        }

        // --- Stage P transposed (k-major) to smem ---
#pragma unroll
        for (int j = 0; j < 8; j++) {
            int col = tc * 8 + j;
            float4 p0 = make_float4(s[0][j], s[1][j], s[2][j], s[3][j]);
            float4 p1 = make_float4(s[4][j], s[5][j], s[6][j], s[7][j]);
            *(float4*)&sPs[col * PS_STRIDE + tr * 8]     = p0;
            *(float4*)&sPs[col * PS_STRIDE + tr * 8 + 4] = p1;
        }
        __syncthreads();

        // --- P @ V: O micro 8x8, contraction over k ---
#pragma unroll 4
        for (int j = 0; j < KT; j++) {
            float4 a0 = *(const float4*)&sPs[j * PS_STRIDE + tr * 8];
            float4 a1 = *(const float4*)&sPs[j * PS_STRIDE + tr * 8 + 4];
            float4 b0 = *(const float4*)&sVs[j * VS_STRIDE + tc * 8];
            float4 b1 = *(const float4*)&sVs[j * VS_STRIDE + tc * 8 + 4];
            float a[8] = {a0.x, a0.y, a0.z, a0.w, a1.x, a1.y, a1.z, a1.w};
            float bv_[8] = {b0.x, b0.y, b0.z, b0.w, b1.x, b1.y, b1.z, b1.w};
#pragma unroll
            for (int i = 0; i < 8; i++)
#pragma unroll
                for (int jd = 0; jd < 8; jd++)
                    acc[i][jd] = fmaf(a[i], bv_[jd], acc[i][jd]);
        }
    }

    // --- Normalize and store ---
#pragma unroll
    for (int i = 0; i < 8; i++) {
        float inv = 1.0f / lrow[i];
        int row = q0 + tr * 8 + i;
        float* optr = O + ((size_t)(b * NN + row)) * DD + h * PP + tc * 8;
        float4 o0, o1;
        o0.x = acc[i][0] * inv; o0.y = acc[i][1] * inv;
        o0.z = acc[i][2] * inv; o0.w = acc[i][3] * inv;
        o1.x = acc[i][4] * inv; o1.y = acc[i][5] * inv;
        o1.z = acc[i][6] * inv; o1.w = acc[i][7] * inv;
        *(float4*)optr       = o0;
        *(float4*)(optr + 4) = o1;
    }
}

// ---------------- launch ----------------
extern "C" void kernel_launch(void* const* d_in, const int* in_sizes, int n_in,
                              void* d_out, int out_size)
{
    const float* queries = (const float*)d_in[0];
    const float* keys    = (const float*)d_in[1];
    const float* values  = (const float*)d_in[2];
    const float* Wq      = (const float*)d_in[3];
    const float* bq      = (const float*)d_in[4];
    const float* Wk      = (const float*)d_in[5];
    const float* bk      = (const float*)d_in[6];
    const float* Wv      = (const float*)d_in[7];
    const float* bv      = (const float*)d_in[8];
    float* out = (float*)d_out;

    float *pq, *pk, *pv;
    cudaGetSymbolAddress((void**)&pq, g_q);
    cudaGetSymbolAddress((void**)&pk, g_k);
    cudaGetSymbolAddress((void**)&pv, g_v);

    dim3 gGrid(DD / BN, RR / BM);      // (4, 64)
    gemm_bias_kernel<<<gGrid, 256>>>(queries, Wq, bq, pq);
    gemm_bias_kernel<<<gGrid, 256>>>(keys,    Wk, bk, pk);
    gemm_bias_kernel<<<gGrid, 256>>>(values,  Wv, bv, pv);

    const int attn_smem = ATTN_SMEM_FLOATS * (int)sizeof(float);   // ~104 KB
    cudaFuncSetAttribute(attn_kernel,
                         cudaFuncAttributeMaxDynamicSharedMemorySize, attn_smem);
    dim3 aGrid(NN / BQ, HH, BB);       // (32, 8, 2)
    attn_kernel<<<aGrid, BQ, attn_smem>>>(pq, pk, pv, out);
}

// round 4
// speedup vs baseline: 2.7127x; 2.3271x over previous
#include <cuda_runtime.h>
#include <cuda_bf16.h>
#include <math_constants.h>
#include <cstdint>

// Problem constants
#define BB   2
#define NN   4096
#define MM   4096
#define DD   512
#define HH   8
#define PP   64
#define RR   (BB * NN)

// ---------------- scratch ----------------
__device__ float g_q[(size_t)BB * NN * DD];
__device__ float g_k[(size_t)BB * MM * DD];
__device__ float g_v[(size_t)BB * MM * DD];

// ---------------- helpers ----------------
__device__ __forceinline__ uint32_t f2tf(float f) {
    uint32_t u;
    asm("cvt.rna.tf32.f32 %0, %1;" : "=r"(u) : "f"(f));
    return u;
}

// D = A(16x8,tf32) @ B(8x8,tf32) + D, fp32 accum. PTX-ISA standard fragments.
__device__ __forceinline__ void mma8(float c[4], const uint32_t a[4],
                                     uint32_t b0, uint32_t b1) {
    asm volatile(
        "mma.sync.aligned.m16n8k8.row.col.f32.tf32.tf32.f32 "
        "{%0,%1,%2,%3}, {%4,%5,%6,%7}, {%8,%9}, {%0,%1,%2,%3};\n"
        : "+f"(c[0]), "+f"(c[1]), "+f"(c[2]), "+f"(c[3])
        : "r"(a[0]), "r"(a[1]), "r"(a[2]), "r"(a[3]), "r"(b0), "r"(b1));
}

// ---------------- Projection GEMM (SIMT fp32, unchanged) ----------------
#define BM 128
#define BN 128
#define BK 16

__global__ __launch_bounds__(256) void gemm_bias_kernel(
    const float* __restrict__ X, const float* __restrict__ W,
    const float* __restrict__ bias, float* __restrict__ Y)
{
    __shared__ float As[BK][BM];
    __shared__ float Bs[BK][BN];

    const int tid = threadIdx.x;
    const int cb  = blockIdx.x * BN;
    const int rb  = blockIdx.y * BM;
    const int tr = tid / 16;
    const int tc = tid % 16;

    float acc[8][8];
#pragma unroll
    for (int i = 0; i < 8; i++)
#pragma unroll
        for (int j = 0; j < 8; j++) acc[i][j] = 0.0f;

    for (int k0 = 0; k0 < DD; k0 += BK) {
#pragma unroll
        for (int t = 0; t < 2; t++) {
            int idx = tid * 2 + t;
            int r = idx / 4, c4 = idx % 4;
            float4 v = *(const float4*)(X + (size_t)(rb + r) * DD + k0 + c4 * 4);
            As[c4 * 4 + 0][r] = v.x; As[c4 * 4 + 1][r] = v.y;
            As[c4 * 4 + 2][r] = v.z; As[c4 * 4 + 3][r] = v.w;
        }
#pragma unroll
        for (int t = 0; t < 2; t++) {
            int idx = tid * 2 + t;
            int r = idx / 32, c4 = idx % 32;
            float4 v = *(const float4*)(W + (size_t)(k0 + r) * DD + cb + c4 * 4);
            *(float4*)&Bs[r][c4 * 4] = v;
        }
        __syncthreads();
#pragma unroll
        for (int k = 0; k < BK; k++) {
            float a[8], b[8];
#pragma unroll
            for (int i = 0; i < 8; i++) a[i] = As[k][tr * 8 + i];
#pragma unroll
            for (int j = 0; j < 8; j++) b[j] = Bs[k][tc * 8 + j];
#pragma unroll
            for (int i = 0; i < 8; i++)
#pragma unroll
                for (int j = 0; j < 8; j++)
                    acc[i][j] = fmaf(a[i], b[j], acc[i][j]);
        }
        __syncthreads();
    }
#pragma unroll
    for (int i = 0; i < 8; i++) {
        int row = rb + tr * 8 + i;
#pragma unroll
        for (int j = 0; j < 8; j += 4) {
            int col = cb + tc * 8 + j;
            float4 o;
            o.x = acc[i][j + 0] + bias[col + 0];
            o.y = acc[i][j + 1] + bias[col + 1];
            o.z = acc[i][j + 2] + bias[col + 2];
            o.w = acc[i][j + 3] + bias[col + 3];
            *(float4*)(Y + (size_t)row * DD + col) = o;
        }
    }
}

// ---------------- Flash attention via mma.sync tf32 ----------------
// CTA = 128 threads (4 warps). BQ = 64 query rows (16 per warp). KT = 64 keys.
// Smem: K tile [64 x 68] (overlaid with P after QK), V tile [64 x 72].
// All smem operands stored as tf32 bit patterns.
#define KT    64
#define KSTR  68   // 68 % 32 == 4 -> conflict-free B/A fragment reads
#define VSTR  72   // 72 % 32 == 8 -> conflict-free B fragment reads

__global__ __launch_bounds__(128) void attn_mma_kernel(
    const float* __restrict__ Q, const float* __restrict__ K,
    const float* __restrict__ V, float* __restrict__ O)
{
    __shared__ uint32_t sKP[KT * KSTR];   // K tile, then P tiles (per-warp rows)
    __shared__ uint32_t sV[KT * VSTR];

    const int tid  = threadIdx.x;
    const int lane = tid & 31;
    const int w    = tid >> 5;       // warp 0..3 -> query rows w*16..w*16+15
    const int gid  = lane >> 2;      // group id 0..7
    const int tig  = lane & 3;       // thread-in-group 0..3

    const int b  = blockIdx.z;
    const int h  = blockIdx.y;
    const int q0 = blockIdx.x * 64;

    const float* Qb = Q + ((size_t)(b * NN + q0 + w * 16)) * DD + h * PP;
    const float* Kb = K + ((size_t)b * MM) * DD + h * PP;
    const float* Vb = V + ((size_t)b * MM) * DD + h * PP;

    // Q fragments, resident all kernel. a0:(gid,tig) a1:(gid+8,tig) a2:(gid,tig+4) a3:(gid+8,tig+4)
    uint32_t qa[8][4];
#pragma unroll
    for (int ks = 0; ks < 8; ks++) {
        int d0 = ks * 8 + tig;
        qa[ks][0] = f2tf(0.125f * __ldg(Qb + (size_t)gid * DD + d0));
        qa[ks][1] = f2tf(0.125f * __ldg(Qb + (size_t)(gid + 8) * DD + d0));
        qa[ks][2] = f2tf(0.125f * __ldg(Qb + (size_t)gid * DD + d0 + 4));
        qa[ks][3] = f2tf(0.125f * __ldg(Qb + (size_t)(gid + 8) * DD + d0 + 4));
    }

    float acc[8][4];
#pragma unroll
    for (int nt = 0; nt < 8; nt++)
#pragma unroll
        for (int c = 0; c < 4; c++) acc[nt][c] = 0.0f;
    float m0 = -CUDART_INF_F, m1 = -CUDART_INF_F, l0 = 0.0f, l1 = 0.0f;

    for (int kt = 0; kt < MM; kt += KT) {
        __syncthreads();   // prior tile's PV reads of sKP(P)/sV complete

        // Load K -> sKP (stride 68) and V -> sV (stride 72), cvt to tf32 at store.
        for (int it = tid; it < KT * 16; it += 128) {
            int key = it >> 4, c4 = it & 15;
            float4 kv = *(const float4*)(Kb + (size_t)(kt + key) * DD + c4 * 4);
            uint32_t* pk = &sKP[key * KSTR + c4 * 4];
            pk[0] = f2tf(kv.x); pk[1] = f2tf(kv.y); pk[2] = f2tf(kv.z); pk[3] = f2tf(kv.w);
            float4 vv = *(const float4*)(Vb + (size_t)(kt + key) * DD + c4 * 4);
            uint32_t* pv = &sV[key * VSTR + c4 * 4];
            pv[0] = f2tf(vv.x); pv[1] = f2tf(vv.y); pv[2] = f2tf(vv.z); pv[3] = f2tf(vv.w);
        }
        __syncthreads();

        // --- QK^T: S_w[16 x 64] ---
        float s[8][4];
#pragma unroll
        for (int nt = 0; nt < 8; nt++) {
            s[nt][0] = s[nt][1] = s[nt][2] = s[nt][3] = 0.0f;
            const uint32_t* krow = &sKP[(nt * 8 + gid) * KSTR];
#pragma unroll
            for (int ks = 0; ks < 8; ks++) {
                uint32_t b0 = krow[ks * 8 + tig];
                uint32_t b1 = krow[ks * 8 + tig + 4];
                mma8(s[nt], qa[ks], b0, b1);
            }
        }

        // --- online softmax (rows gid: c0,c1 ; gid+8: c2,c3) ---
        float mx0 = fmaxf(s[0][0], s[0][1]);
        float mx1 = fmaxf(s[0][2], s[0][3]);
#pragma unroll
        for (int nt = 1; nt < 8; nt++) {
            mx0 = fmaxf(mx0, fmaxf(s[nt][0], s[nt][1]));
            mx1 = fmaxf(mx1, fmaxf(s[nt][2], s[nt][3]));
        }
        mx0 = fmaxf(mx0, __shfl_xor_sync(0xffffffffu, mx0, 1));
        mx0 = fmaxf(mx0, __shfl_xor_sync(0xffffffffu, mx0, 2));
        mx1 = fmaxf(mx1, __shfl_xor_sync(0xffffffffu, mx1, 1));
        mx1 = fmaxf(mx1, __shfl_xor_sync(0xffffffffu, mx1, 2));

        float mn0 = fmaxf(m0, mx0), mn1 = fmaxf(m1, mx1);
        float corr0 = __expf(m0 - mn0), corr1 = __expf(m1 - mn1);
        m0 = mn0; m1 = mn1;

        float sum0 = 0.0f, sum1 = 0.0f;
#pragma unroll
        for (int nt = 0; nt < 8; nt++) {
            s[nt][0] = __expf(s[nt][0] - mn0);
            s[nt][1] = __expf(s[nt][1] - mn0);
            s[nt][2] = __expf(s[nt][2] - mn1);
            s[nt][3] = __expf(s[nt][3] - mn1);
            sum0 += s[nt][0] + s[nt][1];
            sum1 += s[nt][2] + s[nt][3];
        }
        sum0 += __shfl_xor_sync(0xffffffffu, sum0, 1);
        sum0 += __shfl_xor_sync(0xffffffffu, sum0, 2);
        sum1 += __shfl_xor_sync(0xffffffffu, sum1, 1);
        sum1 += __shfl_xor_sync(0xffffffffu, sum1, 2);
        l0 = l0 * corr0 + sum0;
        l1 = l1 * corr1 + sum1;

#pragma unroll
        for (int nt = 0; nt < 8; nt++) {
            acc[nt][0] *= corr0; acc[nt][1] *= corr0;
            acc[nt][2] *= corr1; acc[nt][3] *= corr1;
        }

        __syncthreads();   // everyone done reading K before P overlay

        // --- store P (tf32) into own warp region of sKP ---
        {
            uint32_t* pr0 = &sKP[(w * 16 + gid) * KSTR];
            uint32_t* pr1 = &sKP[(w * 16 + gid + 8) * KSTR];
#pragma unroll
            for (int nt = 0; nt < 8; nt++) {
                int col = nt * 8 + 2 * tig;
                uint2 p0 = make_uint2(f2tf(s[nt][0]), f2tf(s[nt][1]));
                uint2 p1 = make_uint2(f2tf(s[nt][2]), f2tf(s[nt][3]));
                *(uint2*)&pr0[col] = p0;
                *(uint2*)&pr1[col] = p1;
            }
        }
        __syncwarp();

        // --- PV: acc += P_w[16 x 64] @ V[64 x 64] ---
        {
            const uint32_t* pr0 = &sKP[(w * 16 + gid) * KSTR];
            const uint32_t* pr1 = &sKP[(w * 16 + gid + 8) * KSTR];
#pragma unroll
            for (int ks = 0; ks < 8; ks++) {
                uint32_t a[4];
                a[0] = pr0[ks * 8 + tig];
                a[1] = pr1[ks * 8 + tig];
                a[2] = pr0[ks * 8 + tig + 4];
                a[3] = pr1[ks * 8 + tig + 4];
                const uint32_t* vr0 = &sV[(ks * 8 + tig) * VSTR];
                const uint32_t* vr1 = &sV[(ks * 8 + tig + 4) * VSTR];
#pragma unroll
                for (int nt = 0; nt < 8; nt++) {
                    mma8(acc[nt], a, vr0[nt * 8 + gid], vr1[nt * 8 + gid]);
                }
            }
        }
    }

    // --- normalize & store ---
    float inv0 = 1.0f / l0, inv1 = 1.0f / l1;
    float* Ob = O + ((size_t)(b * NN + q0 + w * 16)) * DD + h * PP;
#pragma unroll
    for (int nt = 0; nt < 8; nt++) {
        int col = nt * 8 + 2 * tig;
        float2 o0 = make_float2(acc[nt][0] * inv0, acc[nt][1] * inv0);
        float2 o1 = make_float2(acc[nt][2] * inv1, acc[nt][3] * inv1);
        *(float2*)(Ob + (size_t)gid * DD + col)       = o0;
        *(float2*)(Ob + (size_t)(gid + 8) * DD + col) = o1;
    }
}

// ---------------- launch ----------------
extern "C" void kernel_launch(void* const* d_in, const int* in_sizes, int n_in,
                              void* d_out, int out_size)
{
    const float* queries = (const float*)d_in[0];
    const float* keys    = (const float*)d_in[1];
    const float* values  = (const float*)d_in[2];
    const float* Wq      = (const float*)d_in[3];
    const float* bq      = (const float*)d_in[4];
    const float* Wk      = (const float*)d_in[5];
    const float* bk      = (const float*)d_in[6];
    const float* Wv      = (const float*)d_in[7];
    const float* bv      = (const float*)d_in[8];
    float* out = (float*)d_out;

    float *pq, *pk, *pv;
    cudaGetSymbolAddress((void**)&pq, g_q);
    cudaGetSymbolAddress((void**)&pk, g_k);
    cudaGetSymbolAddress((void**)&pv, g_v);

    dim3 gGrid(DD / BN, RR / BM);
    gemm_bias_kernel<<<gGrid, 256>>>(queries, Wq, bq, pq);
    gemm_bias_kernel<<<gGrid, 256>>>(keys,    Wk, bk, pk);
    gemm_bias_kernel<<<gGrid, 256>>>(values,  Wv, bv, pv);

    dim3 aGrid(NN / 64, HH, BB);   // (64, 8, 2)
    attn_mma_kernel<<<aGrid, 128>>>(pq, pk, pv, out);
}

// round 8
// speedup vs baseline: 4.3767x; 1.6134x over previous
#include <cuda_runtime.h>
#include <math_constants.h>
#include <cstdint>

// Problem constants
#define BB   2
#define NN   4096
#define MM   4096
#define DD   512
#define HH   8
#define PP   64
#define RR   (BB * NN)

// ---------------- scratch ----------------
__device__ float g_q[(size_t)RR * DD];
__device__ float g_k[(size_t)RR * DD];
__device__ float g_v[(size_t)RR * DD];
__device__ float g_xq[(size_t)RR * DD];
__device__ float g_xk[(size_t)RR * DD];
__device__ float g_xv[(size_t)RR * DD];
__device__ float g_wq[(size_t)DD * DD];
__device__ float g_wk[(size_t)DD * DD];
__device__ float g_wv[(size_t)DD * DD];

// ---------------- helpers ----------------
__device__ __forceinline__ uint32_t f2tf(float f) {
    uint32_t u;
    asm("cvt.rna.tf32.f32 %0, %1;" : "=r"(u) : "f"(f));
    return u;
}
__device__ __forceinline__ uint32_t smem_u32(const void* p) {
    uint32_t a;
    asm("{ .reg .u64 t; cvta.to.shared.u64 t, %1; cvt.u32.u64 %0, t; }" : "=r"(a) : "l"(p));
    return a;
}
#define CP_ASYNC16(dst_u32, src) \
    asm volatile("cp.async.cg.shared.global [%0], [%1], 16;" :: "r"(dst_u32), "l"(src))
#define CP_COMMIT() asm volatile("cp.async.commit_group;" ::: "memory")
#define CP_WAIT1()  asm volatile("cp.async.wait_group 1;" ::: "memory")
#define CP_WAIT0()  asm volatile("cp.async.wait_group 0;" ::: "memory")

// D(16x8) += A(16x8,tf32) @ B(8x8,tf32), fp32 accum.
__device__ __forceinline__ void mma8(float c[4], const uint32_t a[4],
                                     uint32_t b0, uint32_t b1) {
    asm volatile(
        "mma.sync.aligned.m16n8k8.row.col.f32.tf32.tf32.f32 "
        "{%0,%1,%2,%3}, {%4,%5,%6,%7}, {%8,%9}, {%0,%1,%2,%3};\n"
        : "+f"(c[0]), "+f"(c[1]), "+f"(c[2]), "+f"(c[3])
        : "r"(a[0]), "r"(a[1]), "r"(a[2]), "r"(a[3]), "r"(b0), "r"(b1));
}

// ================= Pre-round pass: rna-tf32 in gmem =================
__global__ __launch_bounds__(256) void round_tf32_kernel(
    const float4* __restrict__ src, float4* __restrict__ dst, int n4)
{
    int i = blockIdx.x * blockDim.x + threadIdx.x;
    int stride = gridDim.x * blockDim.x;
    for (; i < n4; i += stride) {
        float4 v = src[i];
        v.x = __uint_as_float(f2tf(v.x));
        v.y = __uint_as_float(f2tf(v.y));
        v.z = __uint_as_float(f2tf(v.z));
        v.w = __uint_as_float(f2tf(v.w));
        dst[i] = v;
    }
}

// ================= Projection GEMM via mma tf32 =================
// Y[8192,512] = X @ W + b (X, W pre-rounded to tf32; output rounded to tf32).
// CTA = 128 thr (4 warps), tile M=128 (32 rows/warp), N=64, K-chunks 64,
// cp.async double-buffered. One launch, z selects proj.
#define PXSTR 68
#define PWSTR 72
#define POFF_X0 0
#define POFF_X1 (128 * PXSTR)
#define POFF_W0 (2 * 128 * PXSTR)
#define POFF_W1 (2 * 128 * PXSTR + 64 * PWSTR)
#define PROJ_SMEM_BYTES ((2 * 128 * PXSTR + 2 * 64 * PWSTR) * 4)
#define NCH 8   // 512 / 64

__global__ __launch_bounds__(128) void proj_mma_kernel(
    const float* __restrict__ Xq, const float* __restrict__ Xk, const float* __restrict__ Xv,
    const float* __restrict__ Wq, const float* __restrict__ Wk, const float* __restrict__ Wv,
    const float* __restrict__ bq, const float* __restrict__ bk, const float* __restrict__ bv,
    float* __restrict__ Yq, float* __restrict__ Yk, float* __restrict__ Yv)
{
    extern __shared__ uint32_t smw[];
    const uint32_t smbase = smem_u32(smw);

    const int z = blockIdx.z;
    const float* X    = z == 0 ? Xq : (z == 1 ? Xk : Xv);
    const float* W    = z == 0 ? Wq : (z == 1 ? Wk : Wv);
    const float* bias = z == 0 ? bq : (z == 1 ? bk : bv);
    float*       Y    = z == 0 ? Yq : (z == 1 ? Yk : Yv);

    const int tid  = threadIdx.x;
    const int lane = tid & 31;
    const int w    = tid >> 5;
    const int gid  = lane >> 2;
    const int tig  = lane & 3;
    const int rb   = blockIdx.y * 128;
    const int cb   = blockIdx.x * 64;

    const int ldr = tid >> 4;    // loader row-part 0..7
    const int ldc = tid & 15;    // loader c4 0..15

    // prefetch chunk 0 into buf 0
    {
        const float* Xc = X + (size_t)rb * DD;
#pragma unroll
        for (int l = 0; l < 16; l++) {
            int row = ldr + l * 8;
            CP_ASYNC16(smbase + (uint32_t)(POFF_X0 + row * PXSTR + ldc * 4) * 4,
                       Xc + (size_t)row * DD + ldc * 4);
        }
        const float* Wc = W + cb;
#pragma unroll
        for (int l = 0; l < 8; l++) {
            int row = ldr + l * 8;
            CP_ASYNC16(smbase + (uint32_t)(POFF_W0 + row * PWSTR + ldc * 4) * 4,
                       Wc + (size_t)row * DD + ldc * 4);
        }
        CP_COMMIT();
    }

    float acc0[8][4], acc1[8][4];
#pragma unroll
    for (int nt = 0; nt < 8; nt++)
#pragma unroll
        for (int c = 0; c < 4; c++) { acc0[nt][c] = 0.0f; acc1[nt][c] = 0.0f; }

    for (int ch = 0; ch < NCH; ch++) {
        int cur = ch & 1;
        if (ch + 1 < NCH) {
            int nb = (ch + 1) & 1;
            const float* Xc = X + (size_t)rb * DD + (ch + 1) * 64;
#pragma unroll
            for (int l = 0; l < 16; l++) {
                int row = ldr + l * 8;
                CP_ASYNC16(smbase + (uint32_t)((nb ? POFF_X1 : POFF_X0) + row * PXSTR + ldc * 4) * 4,
                           Xc + (size_t)row * DD + ldc * 4);
            }
            const float* Wc = W + (size_t)((ch + 1) * 64) * DD + cb;
#pragma unroll
            for (int l = 0; l < 8; l++) {
                int row = ldr + l * 8;
                CP_ASYNC16(smbase + (uint32_t)((nb ? POFF_W1 : POFF_W0) + row * PWSTR + ldc * 4) * 4,
                           Wc + (size_t)row * DD + ldc * 4);
            }
            CP_COMMIT();
            CP_WAIT1();
        } else {
            CP_WAIT0();
        }
        __syncthreads();

        const uint32_t* sX = smw + (cur ? POFF_X1 : POFF_X0);
        const uint32_t* sW = smw + (cur ? POFF_W1 : POFF_W0);

#pragma unroll
        for (int ks = 0; ks < 8; ks++) {
            uint32_t a0[4], a1[4];
            const uint32_t* x0 = &sX[(w * 32 + gid) * PXSTR + ks * 8];
            a0[0] = x0[tig];               a0[2] = x0[tig + 4];
            a0[1] = x0[8 * PXSTR + tig];   a0[3] = x0[8 * PXSTR + tig + 4];
            a1[0] = x0[16 * PXSTR + tig];  a1[2] = x0[16 * PXSTR + tig + 4];
            a1[1] = x0[24 * PXSTR + tig];  a1[3] = x0[24 * PXSTR + tig + 4];
            const uint32_t* wr0 = &sW[(ks * 8 + tig) * PWSTR];
            const uint32_t* wr1 = wr0 + 4 * PWSTR;
#pragma unroll
            for (int nt = 0; nt < 8; nt++) {
                uint32_t b0 = wr0[nt * 8 + gid];
                uint32_t b1 = wr1[nt * 8 + gid];
                mma8(acc0[nt], a0, b0, b1);
                mma8(acc1[nt], a1, b0, b1);
            }
        }
        __syncthreads();
    }

    // epilogue: bias + rna-tf32 round + store (so downstream truncation is lossless)
    const int r0 = rb + w * 32 + gid;
#pragma unroll
    for (int nt = 0; nt < 8; nt++) {
        int col = cb + nt * 8 + 2 * tig;
        float2 bv2 = *(const float2*)(bias + col);
        float2 o;
        o.x = __uint_as_float(f2tf(acc0[nt][0] + bv2.x));
        o.y = __uint_as_float(f2tf(acc0[nt][1] + bv2.y));
        *(float2*)(Y + (size_t)r0 * DD + col) = o;
        o.x = __uint_as_float(f2tf(acc0[nt][2] + bv2.x));
        o.y = __uint_as_float(f2tf(acc0[nt][3] + bv2.y));
        *(float2*)(Y + (size_t)(r0 + 8) * DD + col) = o;
        o.x = __uint_as_float(f2tf(acc1[nt][0] + bv2.x));
        o.y = __uint_as_float(f2tf(acc1[nt][1] + bv2.y));
        *(float2*)(Y + (size_t)(r0 + 16) * DD + col) = o;
        o.x = __uint_as_float(f2tf(acc1[nt][2] + bv2.x));
        o.y = __uint_as_float(f2tf(acc1[nt][3] + bv2.y));
        *(float2*)(Y + (size_t)(r0 + 24) * DD + col) = o;
    }
}

// ================= Flash attention via mma tf32 + cp.async =================
// CTA = 128 thr (4 warps), 64 query rows (16/warp), KV tile 64 keys,
// double-buffered K/V (already tf32 in gmem -> truncation lossless),
// P in dedicated smem.
#define KT    64
#define NTIL  (MM / KT)
#define KSTR  68
#define VSTR  72
#define PSTR  68
#define OFF_K0 0
#define OFF_K1 (64 * KSTR)
#define OFF_V0 (2 * 64 * KSTR)
#define OFF_V1 (2 * 64 * KSTR + 64 * VSTR)
#define OFF_P  (2 * 64 * KSTR + 2 * 64 * VSTR)
#define ATTN_SMEM_BYTES ((OFF_P + 64 * PSTR) * 4)

__global__ __launch_bounds__(128) void attn_mma_kernel(
    const float* __restrict__ Q, const float* __restrict__ K,
    const float* __restrict__ V, float* __restrict__ O)
{
    extern __shared__ uint32_t smw[];
    const uint32_t smbase = smem_u32(smw);

    const int tid  = threadIdx.x;
    const int lane = tid & 31;
    const int w    = tid >> 5;
    const int gid  = lane >> 2;
    const int tig  = lane & 3;

    const int b  = blockIdx.z;
    const int h  = blockIdx.y;
    const int q0 = blockIdx.x * 64;

    const float* Qb = Q + ((size_t)(b * NN + q0 + w * 16)) * DD + h * PP;
    const float* Kb = K + ((size_t)b * MM) * DD + h * PP;
    const float* Vb = V + ((size_t)b * MM) * DD + h * PP;

    const int ldr = tid >> 4;   // 0..7
    const int ldc = tid & 15;   // 0..15

    // prefetch KV tile 0 into buf 0
    {
#pragma unroll
        for (int l = 0; l < 8; l++) {
            int key = ldr + l * 8;
            const float* kp = Kb + (size_t)key * DD + ldc * 4;
            const float* vp = Vb + (size_t)key * DD + ldc * 4;
            CP_ASYNC16(smbase + (uint32_t)(OFF_K0 + key * KSTR + ldc * 4) * 4, kp);
            CP_ASYNC16(smbase + (uint32_t)(OFF_V0 + key * VSTR + ldc * 4) * 4, vp);
        }
        CP_COMMIT();
    }

    // Q fragments (q already tf32; 0.125 scale is exact) resident all kernel.
    uint32_t qa[8][4];
#pragma unroll
    for (int ks = 0; ks < 8; ks++) {
        int d0 = ks * 8 + tig;
        qa[ks][0] = __float_as_uint(0.125f * __ldg(Qb + (size_t)gid * DD + d0));
        qa[ks][1] = __float_as_uint(0.125f * __ldg(Qb + (size_t)(gid + 8) * DD + d0));
        qa[ks][2] = __float_as_uint(0.125f * __ldg(Qb + (size_t)gid * DD + d0 + 4));
        qa[ks][3] = __float_as_uint(0.125f * __ldg(Qb + (size_t)(gid + 8) * DD + d0 + 4));
    }

    float acc[8][4];
#pragma unroll
    for (int nt = 0; nt < 8; nt++)
#pragma unroll
        for (int c = 0; c < 4; c++) acc[nt][c] = 0.0f;
    float m0 = -CUDART_INF_F, m1 = -CUDART_INF_F, l0 = 0.0f, l1 = 0.0f;

    for (int t = 0; t < NTIL; t++) {
        int cur = t & 1;
        if (t + 1 < NTIL) {
            int nb = (t + 1) & 1;
            const float* Ks = Kb + (size_t)(t + 1) * KT * DD;
            const float* Vs = Vb + (size_t)(t + 1) * KT * DD;
#pragma unroll
            for (int l = 0; l < 8; l++) {
                int key = ldr + l * 8;
                CP_ASYNC16(smbase + (uint32_t)((nb ? OFF_K1 : OFF_K0) + key * KSTR + ldc * 4) * 4,
                           Ks + (size_t)key * DD + ldc * 4);
                CP_ASYNC16(smbase + (uint32_t)((nb ? OFF_V1 : OFF_V0) + key * VSTR + ldc * 4) * 4,
                           Vs + (size_t)key * DD + ldc * 4);
            }
            CP_COMMIT();
            CP_WAIT1();
        } else {
            CP_WAIT0();
        }
        __syncthreads();

        const uint32_t* sK = smw + (cur ? OFF_K1 : OFF_K0);
        const uint32_t* sV = smw + (cur ? OFF_V1 : OFF_V0);
        uint32_t* sP = smw + OFF_P;

        // --- QK^T: S_w[16 x 64] ---
        float s[8][4];
#pragma unroll
        for (int nt = 0; nt < 8; nt++) {
            s[nt][0] = s[nt][1] = s[nt][2] = s[nt][3] = 0.0f;
            const uint32_t* krow = &sK[(nt * 8 + gid) * KSTR];
#pragma unroll
            for (int ks = 0; ks < 8; ks++) {
                uint32_t b0 = krow[ks * 8 + tig];
                uint32_t b1 = krow[ks * 8 + tig + 4];
                mma8(s[nt], qa[ks], b0, b1);
            }
        }

        // --- online softmax ---
        float mx0 = fmaxf(s[0][0], s[0][1]);
        float mx1 = fmaxf(s[0][2], s[0][3]);
#pragma unroll
        for (int nt = 1; nt < 8; nt++) {
            mx0 = fmaxf(mx0, fmaxf(s[nt][0], s[nt][1]));
            mx1 = fmaxf(mx1, fmaxf(s[nt][2], s[nt][3]));
        }
        mx0 = fmaxf(mx0, __shfl_xor_sync(0xffffffffu, mx0, 1));
        mx0 = fmaxf(mx0, __shfl_xor_sync(0xffffffffu, mx0, 2));
        mx1 = fmaxf(mx1, __shfl_xor_sync(0xffffffffu, mx1, 1));
        mx1 = fmaxf(mx1, __shfl_xor_sync(0xffffffffu, mx1, 2));

        float mn0 = fmaxf(m0, mx0), mn1 = fmaxf(m1, mx1);
        float corr0 = __expf(m0 - mn0), corr1 = __expf(m1 - mn1);
        m0 = mn0; m1 = mn1;

        float sum0 = 0.0f, sum1 = 0.0f;
#pragma unroll
        for (int nt = 0; nt < 8; nt++) {
            s[nt][0] = __expf(s[nt][0] - mn0);
            s[nt][1] = __expf(s[nt][1] - mn0);
            s[nt][2] = __expf(s[nt][2] - mn1);
            s[nt][3] = __expf(s[nt][3] - mn1);
            sum0 += s[nt][0] + s[nt][1];
            sum1 += s[nt][2] + s[nt][3];
        }
        sum0 += __shfl_xor_sync(0xffffffffu, sum0, 1);
        sum0 += __shfl_xor_sync(0xffffffffu, sum0, 2);
        sum1 += __shfl_xor_sync(0xffffffffu, sum1, 1);
        sum1 += __shfl_xor_sync(0xffffffffu, sum1, 2);
        l0 = l0 * corr0 + sum0;
        l1 = l1 * corr1 + sum1;

#pragma unroll
        for (int nt = 0; nt < 8; nt++) {
            acc[nt][0] *= corr0; acc[nt][1] *= corr0;
            acc[nt][2] *= corr1; acc[nt][3] *= corr1;
        }

        // --- store P (rna tf32) into own warp region ---
        {
            uint32_t* pr0 = &sP[(w * 16 + gid) * PSTR];
            uint32_t* pr1 = &sP[(w * 16 + gid + 8) * PSTR];
#pragma unroll
            for (int nt = 0; nt < 8; nt++) {
                int col = nt * 8 + 2 * tig;
                uint2 p0 = make_uint2(f2tf(s[nt][0]), f2tf(s[nt][1]));
                uint2 p1 = make_uint2(f2tf(s[nt][2]), f2tf(s[nt][3]));
                *(uint2*)&pr0[col] = p0;
                *(uint2*)&pr1[col] = p1;
            }
        }
        __syncwarp();

        // --- PV: acc += P_w @ V ---
        {
            const uint32_t* pr0 = &sP[(w * 16 + gid) * PSTR];
            const uint32_t* pr1 = &sP[(w * 16 + gid + 8) * PSTR];
#pragma unroll
            for (int ks = 0; ks < 8; ks++) {
                uint32_t a[4];
                a[0] = pr0[ks * 8 + tig];
                a[1] = pr1[ks * 8 + tig];
                a[2] = pr0[ks * 8 + tig + 4];
                a[3] = pr1[ks * 8 + tig + 4];
                const uint32_t* vr0 = &sV[(ks * 8 + tig) * VSTR];
                const uint32_t* vr1 = &sV[(ks * 8 + tig + 4) * VSTR];
#pragma unroll
                for (int nt = 0; nt < 8; nt++) {
                    mma8(acc[nt], a, vr0[nt * 8 + gid], vr1[nt * 8 + gid]);
                }
            }
        }
        __syncthreads();   // all warps done with this K/V buffer before re-prefetch
    }

    // --- normalize & store ---
    float inv0 = 1.0f / l0, inv1 = 1.0f / l1;
    float* Ob = O + ((size_t)(b * NN + q0 + w * 16)) * DD + h * PP;
#pragma unroll
    for (int nt = 0; nt < 8; nt++) {
        int col = nt * 8 + 2 * tig;
        float2 o0 = make_float2(acc[nt][0] * inv0, acc[nt][1] * inv0);
        float2 o1 = make_float2(acc[nt][2] * inv1, acc[nt][3] * inv1);
        *(float2*)(Ob + (size_t)gid * DD + col)       = o0;
        *(float2*)(Ob + (size_t)(gid + 8) * DD + col) = o1;
    }
}

// ---------------- launch ----------------
extern "C" void kernel_launch(void* const* d_in, const int* in_sizes, int n_in,
                              void* d_out, int out_size)
{
    const float* queries = (const float*)d_in[0];
    const float* keys    = (const float*)d_in[1];
    const float* values  = (const float*)d_in[2];
    const float* Wq      = (const float*)d_in[3];
    const float* bq      = (const float*)d_in[4];
    const float* Wk      = (const float*)d_in[5];
    const float* bk      = (const float*)d_in[6];
    const float* Wv      = (const float*)d_in[7];
    const float* bv      = (const float*)d_in[8];
    float* out = (float*)d_out;

    float *pq, *pk, *pv, *pxq, *pxk, *pxv, *pwq, *pwk, *pwv;
    cudaGetSymbolAddress((void**)&pq,  g_q);
    cudaGetSymbolAddress((void**)&pk,  g_k);
    cudaGetSymbolAddress((void**)&pv,  g_v);
    cudaGetSymbolAddress((void**)&pxq, g_xq);
    cudaGetSymbolAddress((void**)&pxk, g_xk);
    cudaGetSymbolAddress((void**)&pxv, g_xv);
    cudaGetSymbolAddress((void**)&pwq, g_wq);
    cudaGetSymbolAddress((void**)&pwk, g_wk);
    cudaGetSymbolAddress((void**)&pwv, g_wv);

    // Pre-round inputs to rna-tf32 so later HMMA truncation is lossless.
    const int nX4 = (RR * DD) / 4;     // 1048576
    const int nW4 = (DD * DD) / 4;     // 65536
    round_tf32_kernel<<<2048, 256>>>((const float4*)queries, (float4*)pxq, nX4);
    round_tf32_kernel<<<2048, 256>>>((const float4*)keys,    (float4*)pxk, nX4);
    round_tf32_kernel<<<2048, 256>>>((const float4*)values,  (float4*)pxv, nX4);
    round_tf32_kernel<<<256, 256>>>((const float4*)Wq, (float4*)pwq, nW4);
    round_tf32_kernel<<<256, 256>>>((const float4*)Wk, (float4*)pwk, nW4);
    round_tf32_kernel<<<256, 256>>>((const float4*)Wv, (float4*)pwv, nW4);

    cudaFuncSetAttribute(proj_mma_kernel,
                         cudaFuncAttributeMaxDynamicSharedMemorySize, PROJ_SMEM_BYTES);
    dim3 pGrid(DD / 64, RR / 128, 3);   // (8, 64, 3)
    proj_mma_kernel<<<pGrid, 128, PROJ_SMEM_BYTES>>>(
        pxq, pxk, pxv, pwq, pwk, pwv, bq, bk, bv, pq, pk, pv);

    cudaFuncSetAttribute(attn_mma_kernel,
                         cudaFuncAttributeMaxDynamicSharedMemorySize, ATTN_SMEM_BYTES);
    dim3 aGrid(NN / 64, HH, BB);        // (64, 8, 2)
    attn_mma_kernel<<<aGrid, 128, ATTN_SMEM_BYTES>>>(pq, pk, pv, out);
}

// round 9
// speedup vs baseline: 4.7973x; 1.0961x over previous
#include <cuda_runtime.h>
#include <math_constants.h>
#include <cstdint>

// Problem constants
#define BB   2
#define NN   4096
#define MM   4096
#define DD   512
#define HH   8
#define PP   64
#define RR   (BB * NN)

// ---------------- scratch ----------------
__device__ float g_q[(size_t)RR * DD];
__device__ float g_k[(size_t)RR * DD];
__device__ float g_v[(size_t)RR * DD];
__device__ float g_xq[(size_t)RR * DD];
__device__ float g_xk[(size_t)RR * DD];
__device__ float g_xv[(size_t)RR * DD];
__device__ float g_wq[(size_t)DD * DD];
__device__ float g_wk[(size_t)DD * DD];
__device__ float g_wv[(size_t)DD * DD];

// ---------------- helpers ----------------
__device__ __forceinline__ uint32_t f2tf(float f) {
    uint32_t u;
    asm("cvt.rna.tf32.f32 %0, %1;" : "=r"(u) : "f"(f));
    return u;
}
__device__ __forceinline__ uint32_t smem_u32(const void* p) {
    uint32_t a;
    asm("{ .reg .u64 t; cvta.to.shared.u64 t, %1; cvt.u32.u64 %0, t; }" : "=r"(a) : "l"(p));
    return a;
}
#define CP_ASYNC16(dst_u32, src) \
    asm volatile("cp.async.cg.shared.global [%0], [%1], 16;" :: "r"(dst_u32), "l"(src))
#define CP_COMMIT() asm volatile("cp.async.commit_group;" ::: "memory")
#define CP_WAIT1()  asm volatile("cp.async.wait_group 1;" ::: "memory")
#define CP_WAIT0()  asm volatile("cp.async.wait_group 0;" ::: "memory")

// D(16x8) += A(16x8,tf32) @ B(8x8,tf32), fp32 accum.
__device__ __forceinline__ void mma8(float c[4], const uint32_t a[4],
                                     uint32_t b0, uint32_t b1) {
    asm volatile(
        "mma.sync.aligned.m16n8k8.row.col.f32.tf32.tf32.f32 "
        "{%0,%1,%2,%3}, {%4,%5,%6,%7}, {%8,%9}, {%0,%1,%2,%3};\n"
        : "+f"(c[0]), "+f"(c[1]), "+f"(c[2]), "+f"(c[3])
        : "r"(a[0]), "r"(a[1]), "r"(a[2]), "r"(a[3]), "r"(b0), "r"(b1));
}

// ================= Pre-round pass: rna-tf32 in gmem =================
__global__ __launch_bounds__(256) void round_tf32_kernel(
    const float4* __restrict__ src, float4* __restrict__ dst, int n4)
{
    int i = blockIdx.x * blockDim.x + threadIdx.x;
    int stride = gridDim.x * blockDim.x;
    for (; i < n4; i += stride) {
        float4 v = src[i];
        v.x = __uint_as_float(f2tf(v.x));
        v.y = __uint_as_float(f2tf(v.y));
        v.z = __uint_as_float(f2tf(v.z));
        v.w = __uint_as_float(f2tf(v.w));
        dst[i] = v;
    }
}

// ================= Projection GEMM via mma tf32 =================
#define PXSTR 68
#define PWSTR 72
#define POFF_X0 0
#define POFF_X1 (128 * PXSTR)
#define POFF_W0 (2 * 128 * PXSTR)
#define POFF_W1 (2 * 128 * PXSTR + 64 * PWSTR)
#define PROJ_SMEM_BYTES ((2 * 128 * PXSTR + 2 * 64 * PWSTR) * 4)
#define NCH 8   // 512 / 64

__global__ __launch_bounds__(128) void proj_mma_kernel(
    const float* __restrict__ Xq, const float* __restrict__ Xk, const float* __restrict__ Xv,
    const float* __restrict__ Wq, const float* __restrict__ Wk, const float* __restrict__ Wv,
    const float* __restrict__ bq, const float* __restrict__ bk, const float* __restrict__ bv,
    float* __restrict__ Yq, float* __restrict__ Yk, float* __restrict__ Yv)
{
    extern __shared__ uint32_t smw[];
    const uint32_t smbase = smem_u32(smw);

    const int z = blockIdx.z;
    const float* X    = z == 0 ? Xq : (z == 1 ? Xk : Xv);
    const float* W    = z == 0 ? Wq : (z == 1 ? Wk : Wv);
    const float* bias = z == 0 ? bq : (z == 1 ? bk : bv);
    float*       Y    = z == 0 ? Yq : (z == 1 ? Yk : Yv);

    const int tid  = threadIdx.x;
    const int lane = tid & 31;
    const int w    = tid >> 5;
    const int gid  = lane >> 2;
    const int tig  = lane & 3;
    const int rb   = blockIdx.y * 128;
    const int cb   = blockIdx.x * 64;

    const int ldr = tid >> 4;
    const int ldc = tid & 15;

    {
        const float* Xc = X + (size_t)rb * DD;
#pragma unroll
        for (int l = 0; l < 16; l++) {
            int row = ldr + l * 8;
            CP_ASYNC16(smbase + (uint32_t)(POFF_X0 + row * PXSTR + ldc * 4) * 4,
                       Xc + (size_t)row * DD + ldc * 4);
        }
        const float* Wc = W + cb;
#pragma unroll
        for (int l = 0; l < 8; l++) {
            int row = ldr + l * 8;
            CP_ASYNC16(smbase + (uint32_t)(POFF_W0 + row * PWSTR + ldc * 4) * 4,
                       Wc + (size_t)row * DD + ldc * 4);
        }
        CP_COMMIT();
    }

    float acc0[8][4], acc1[8][4];
#pragma unroll
    for (int nt = 0; nt < 8; nt++)
#pragma unroll
        for (int c = 0; c < 4; c++) { acc0[nt][c] = 0.0f; acc1[nt][c] = 0.0f; }

    for (int ch = 0; ch < NCH; ch++) {
        int cur = ch & 1;
        if (ch + 1 < NCH) {
            int nb = (ch + 1) & 1;
            const float* Xc = X + (size_t)rb * DD + (ch + 1) * 64;
#pragma unroll
            for (int l = 0; l < 16; l++) {
                int row = ldr + l * 8;
                CP_ASYNC16(smbase + (uint32_t)((nb ? POFF_X1 : POFF_X0) + row * PXSTR + ldc * 4) * 4,
                           Xc + (size_t)row * DD + ldc * 4);
            }
            const float* Wc = W + (size_t)((ch + 1) * 64) * DD + cb;
#pragma unroll
            for (int l = 0; l < 8; l++) {
                int row = ldr + l * 8;
                CP_ASYNC16(smbase + (uint32_t)((nb ? POFF_W1 : POFF_W0) + row * PWSTR + ldc * 4) * 4,
                           Wc + (size_t)row * DD + ldc * 4);
            }
            CP_COMMIT();
            CP_WAIT1();
        } else {
            CP_WAIT0();
        }
        __syncthreads();

        const uint32_t* sX = smw + (cur ? POFF_X1 : POFF_X0);
        const uint32_t* sW = smw + (cur ? POFF_W1 : POFF_W0);

#pragma unroll
        for (int ks = 0; ks < 8; ks++) {
            uint32_t a0[4], a1[4];
            const uint32_t* x0 = &sX[(w * 32 + gid) * PXSTR + ks * 8];
            a0[0] = x0[tig];               a0[2] = x0[tig + 4];
            a0[1] = x0[8 * PXSTR + tig];   a0[3] = x0[8 * PXSTR + tig + 4];
            a1[0] = x0[16 * PXSTR + tig];  a1[2] = x0[16 * PXSTR + tig + 4];
            a1[1] = x0[24 * PXSTR + tig];  a1[3] = x0[24 * PXSTR + tig + 4];
            const uint32_t* wr0 = &sW[(ks * 8 + tig) * PWSTR];
            const uint32_t* wr1 = wr0 + 4 * PWSTR;
#pragma unroll
            for (int nt = 0; nt < 8; nt++) {
                uint32_t b0 = wr0[nt * 8 + gid];
                uint32_t b1 = wr1[nt * 8 + gid];
                mma8(acc0[nt], a0, b0, b1);
                mma8(acc1[nt], a1, b0, b1);
            }
        }
        __syncthreads();
    }

    const int r0 = rb + w * 32 + gid;
#pragma unroll
    for (int nt = 0; nt < 8; nt++) {
        int col = cb + nt * 8 + 2 * tig;
        float2 bv2 = *(const float2*)(bias + col);
        float2 o;
        o.x = __uint_as_float(f2tf(acc0[nt][0] + bv2.x));
        o.y = __uint_as_float(f2tf(acc0[nt][1] + bv2.y));
        *(float2*)(Y + (size_t)r0 * DD + col) = o;
        o.x = __uint_as_float(f2tf(acc0[nt][2] + bv2.x));
        o.y = __uint_as_float(f2tf(acc0[nt][3] + bv2.y));
        *(float2*)(Y + (size_t)(r0 + 8) * DD + col) = o;
        o.x = __uint_as_float(f2tf(acc1[nt][0] + bv2.x));
        o.y = __uint_as_float(f2tf(acc1[nt][1] + bv2.y));
        *(float2*)(Y + (size_t)(r0 + 16) * DD + col) = o;
        o.x = __uint_as_float(f2tf(acc1[nt][2] + bv2.x));
        o.y = __uint_as_float(f2tf(acc1[nt][3] + bv2.y));
        *(float2*)(Y + (size_t)(r0 + 24) * DD + col) = o;
    }
}

// ================= Flash attention: 32 query rows per warp =================
// CTA = 128 thr (4 warps), 128 query rows (32/warp, two 16-row m-tiles),
// KV tile 64 keys double-buffered. Every K/V B-fragment load now feeds
// TWO MMAs (one per m-tile): smem traffic per FLOP ~halved vs R8.
#define KT    64
#define NTIL  (MM / KT)
#define KSTR  68
#define VSTR  72
#define PSTR  68
#define OFF_K0 0
#define OFF_K1 (64 * KSTR)
#define OFF_V0 (2 * 64 * KSTR)
#define OFF_V1 (2 * 64 * KSTR + 64 * VSTR)
#define OFF_P  (2 * 64 * KSTR + 2 * 64 * VSTR)
#define ATTN_SMEM_BYTES ((OFF_P + 128 * PSTR) * 4)   // 104 KB

// Online-softmax update for one 16-row group (components i0,i1 of s[][4]).
#define SOFTMAX2(sarr, i0, i1, mvar, lvar, accarr) do {                       \
    float _mx = fmaxf(sarr[0][i0], sarr[0][i1]);                              \
    _Pragma("unroll")                                                         \
    for (int _nt = 1; _nt < 8; _nt++)                                         \
        _mx = fmaxf(_mx, fmaxf(sarr[_nt][i0], sarr[_nt][i1]));                \
    _mx = fmaxf(_mx, __shfl_xor_sync(0xffffffffu, _mx, 1));                   \
    _mx = fmaxf(_mx, __shfl_xor_sync(0xffffffffu, _mx, 2));                   \
    float _mn = fmaxf(mvar, _mx);                                             \
    float _corr = __expf(mvar - _mn);                                         \
    mvar = _mn;                                                               \
    float _sum = 0.0f;                                                        \
    _Pragma("unroll")                                                         \
    for (int _nt = 0; _nt < 8; _nt++) {                                       \
        sarr[_nt][i0] = __expf(sarr[_nt][i0] - _mn);                          \
        sarr[_nt][i1] = __expf(sarr[_nt][i1] - _mn);                          \
        _sum += sarr[_nt][i0] + sarr[_nt][i1];                                \
    }                                                                         \
    _sum += __shfl_xor_sync(0xffffffffu, _sum, 1);                            \
    _sum += __shfl_xor_sync(0xffffffffu, _sum, 2);                            \
    lvar = lvar * _corr + _sum;                                               \
    _Pragma("unroll")                                                         \
    for (int _nt = 0; _nt < 8; _nt++) {                                       \
        accarr[_nt][i0] *= _corr;                                             \
        accarr[_nt][i1] *= _corr;                                             \
    }                                                                         \
} while (0)

__global__ void __launch_bounds__(128, 2) attn_mma_kernel(
    const float* __restrict__ Q, const float* __restrict__ K,
    const float* __restrict__ V, float* __restrict__ O)
{
    extern __shared__ uint32_t smw[];
    const uint32_t smbase = smem_u32(smw);

    const int tid  = threadIdx.x;
    const int lane = tid & 31;
    const int w    = tid >> 5;       // warp -> query rows w*32 .. w*32+31
    const int gid  = lane >> 2;
    const int tig  = lane & 3;

    const int b  = blockIdx.z;
    const int h  = blockIdx.y;
    const int q0 = blockIdx.x * 128;

    const float* Qb = Q + ((size_t)(b * NN + q0 + w * 32)) * DD + h * PP;
    const float* Kb = K + ((size_t)b * MM) * DD + h * PP;
    const float* Vb = V + ((size_t)b * MM) * DD + h * PP;

    const int ldr = tid >> 4;   // 0..7
    const int ldc = tid & 15;   // 0..15

    // prefetch KV tile 0 into buf 0
    {
#pragma unroll
        for (int l = 0; l < 8; l++) {
            int key = ldr + l * 8;
            CP_ASYNC16(smbase + (uint32_t)(OFF_K0 + key * KSTR + ldc * 4) * 4,
                       Kb + (size_t)key * DD + ldc * 4);
            CP_ASYNC16(smbase + (uint32_t)(OFF_V0 + key * VSTR + ldc * 4) * 4,
                       Vb + (size_t)key * DD + ldc * 4);
        }
        CP_COMMIT();
    }

    // Q fragments for two m-tiles (q already tf32; 0.125 scale exact).
    uint32_t qa0[8][4], qa1[8][4];
#pragma unroll
    for (int ks = 0; ks < 8; ks++) {
        int d0 = ks * 8 + tig;
        qa0[ks][0] = __float_as_uint(0.125f * __ldg(Qb + (size_t)gid * DD + d0));
        qa0[ks][1] = __float_as_uint(0.125f * __ldg(Qb + (size_t)(gid + 8) * DD + d0));
        qa0[ks][2] = __float_as_uint(0.125f * __ldg(Qb + (size_t)gid * DD + d0 + 4));
        qa0[ks][3] = __float_as_uint(0.125f * __ldg(Qb + (size_t)(gid + 8) * DD + d0 + 4));
        qa1[ks][0] = __float_as_uint(0.125f * __ldg(Qb + (size_t)(gid + 16) * DD + d0));
        qa1[ks][1] = __float_as_uint(0.125f * __ldg(Qb + (size_t)(gid + 24) * DD + d0));
        qa1[ks][2] = __float_as_uint(0.125f * __ldg(Qb + (size_t)(gid + 16) * DD + d0 + 4));
        qa1[ks][3] = __float_as_uint(0.125f * __ldg(Qb + (size_t)(gid + 24) * DD + d0 + 4));
    }

    float acc0[8][4], acc1[8][4];
#pragma unroll
    for (int nt = 0; nt < 8; nt++)
#pragma unroll
        for (int c = 0; c < 4; c++) { acc0[nt][c] = 0.0f; acc1[nt][c] = 0.0f; }
    float m00 = -CUDART_INF_F, m01 = -CUDART_INF_F;
    float m10 = -CUDART_INF_F, m11 = -CUDART_INF_F;
    float l00 = 0.0f, l01 = 0.0f, l10 = 0.0f, l11 = 0.0f;

    for (int t = 0; t < NTIL; t++) {
        int cur = t & 1;
        if (t + 1 < NTIL) {
            int nb = (t + 1) & 1;
            const float* Ks = Kb + (size_t)(t + 1) * KT * DD;
            const float* Vs = Vb + (size_t)(t + 1) * KT * DD;
#pragma unroll
            for (int l = 0; l < 8; l++) {
                int key = ldr + l * 8;
                CP_ASYNC16(smbase + (uint32_t)((nb ? OFF_K1 : OFF_K0) + key * KSTR + ldc * 4) * 4,
                           Ks + (size_t)key * DD + ldc * 4);
                CP_ASYNC16(smbase + (uint32_t)((nb ? OFF_V1 : OFF_V0) + key * VSTR + ldc * 4) * 4,
                           Vs + (size_t)key * DD + ldc * 4);
            }
            CP_COMMIT();
            CP_WAIT1();
        } else {
            CP_WAIT0();
        }
        __syncthreads();

        const uint32_t* sK = smw + (cur ? OFF_K1 : OFF_K0);
        const uint32_t* sV = smw + (cur ? OFF_V1 : OFF_V0);
        uint32_t* sP = smw + OFF_P;

        // --- QK^T: S_w[32 x 64], B loads shared by both m-tiles ---
        float s0[8][4], s1[8][4];
#pragma unroll
        for (int nt = 0; nt < 8; nt++) {
            s0[nt][0] = s0[nt][1] = s0[nt][2] = s0[nt][3] = 0.0f;
            s1[nt][0] = s1[nt][1] = s1[nt][2] = s1[nt][3] = 0.0f;
            const uint32_t* krow = &sK[(nt * 8 + gid) * KSTR];
#pragma unroll
            for (int ks = 0; ks < 8; ks++) {
                uint32_t b0 = krow[ks * 8 + tig];
                uint32_t b1 = krow[ks * 8 + tig + 4];
                mma8(s0[nt], qa0[ks], b0, b1);
                mma8(s1[nt], qa1[ks], b0, b1);
            }
        }

        // --- online softmax: four 16-row groups ---
        SOFTMAX2(s0, 0, 1, m00, l00, acc0);
        SOFTMAX2(s0, 2, 3, m01, l01, acc0);
        SOFTMAX2(s1, 0, 1, m10, l10, acc1);
        SOFTMAX2(s1, 2, 3, m11, l11, acc1);

        // --- store P (rna tf32) into own warp region (32 rows) ---
        {
            uint32_t* pr0 = &sP[(w * 32 + gid) * PSTR];
            uint32_t* pr1 = pr0 + 8 * PSTR;
            uint32_t* pr2 = pr0 + 16 * PSTR;
            uint32_t* pr3 = pr0 + 24 * PSTR;
#pragma unroll
            for (int nt = 0; nt < 8; nt++) {
                int col = nt * 8 + 2 * tig;
                *(uint2*)&pr0[col] = make_uint2(f2tf(s0[nt][0]), f2tf(s0[nt][1]));
                *(uint2*)&pr1[col] = make_uint2(f2tf(s0[nt][2]), f2tf(s0[nt][3]));
                *(uint2*)&pr2[col] = make_uint2(f2tf(s1[nt][0]), f2tf(s1[nt][1]));
                *(uint2*)&pr3[col] = make_uint2(f2tf(s1[nt][2]), f2tf(s1[nt][3]));
            }
        }
        __syncwarp();

        // --- PV: acc += P_w[32 x 64] @ V, V loads shared by both m-tiles ---
        {
            const uint32_t* pr0 = &sP[(w * 32 + gid) * PSTR];
            const uint32_t* pr1 = pr0 + 8 * PSTR;
            const uint32_t* pr2 = pr0 + 16 * PSTR;
            const uint32_t* pr3 = pr0 + 24 * PSTR;
#pragma unroll
            for (int ks = 0; ks < 8; ks++) {
                uint32_t a0[4], a1[4];
                a0[0] = pr0[ks * 8 + tig];
                a0[1] = pr1[ks * 8 + tig];
                a0[2] = pr0[ks * 8 + tig + 4];
                a0[3] = pr1[ks * 8 + tig + 4];
                a1[0] = pr2[ks * 8 + tig];
                a1[1] = pr3[ks * 8 + tig];
                a1[2] = pr2[ks * 8 + tig + 4];
                a1[3] = pr3[ks * 8 + tig + 4];
                const uint32_t* vr0 = &sV[(ks * 8 + tig) * VSTR];
                const uint32_t* vr1 = &sV[(ks * 8 + tig + 4) * VSTR];
#pragma unroll
                for (int nt = 0; nt < 8; nt++) {
                    uint32_t b0 = vr0[nt * 8 + gid];
                    uint32_t b1 = vr1[nt * 8 + gid];
                    mma8(acc0[nt], a0, b0, b1);
                    mma8(acc1[nt], a1, b0, b1);
                }
            }
        }
        __syncthreads();   // all warps done with this K/V buffer before re-prefetch
    }

    // --- normalize & store (four 16-row groups) ---
    float i00 = 1.0f / l00, i01 = 1.0f / l01, i10 = 1.0f / l10, i11 = 1.0f / l11;
    float* Ob = O + ((size_t)(b * NN + q0 + w * 32)) * DD + h * PP;
#pragma unroll
    for (int nt = 0; nt < 8; nt++) {
        int col = nt * 8 + 2 * tig;
        *(float2*)(Ob + (size_t)gid * DD + col) =
            make_float2(acc0[nt][0] * i00, acc0[nt][1] * i00);
        *(float2*)(Ob + (size_t)(gid + 8) * DD + col) =
            make_float2(acc0[nt][2] * i01, acc0[nt][3] * i01);
        *(float2*)(Ob + (size_t)(gid + 16) * DD + col) =
            make_float2(acc1[nt][0] * i10, acc1[nt][1] * i10);
        *(float2*)(Ob + (size_t)(gid + 24) * DD + col) =
            make_float2(acc1[nt][2] * i11, acc1[nt][3] * i11);
    }
}

// ---------------- launch ----------------
extern "C" void kernel_launch(void* const* d_in, const int* in_sizes, int n_in,
                              void* d_out, int out_size)
{
    const float* queries = (const float*)d_in[0];
    const float* keys    = (const float*)d_in[1];
    const float* values  = (const float*)d_in[2];
    const float* Wq      = (const float*)d_in[3];
    const float* bq      = (const float*)d_in[4];
    const float* Wk      = (const float*)d_in[5];
    const float* bk      = (const float*)d_in[6];
    const float* Wv      = (const float*)d_in[7];
    const float* bv      = (const float*)d_in[8];
    float* out = (float*)d_out;

    float *pq, *pk, *pv, *pxq, *pxk, *pxv, *pwq, *pwk, *pwv;
    cudaGetSymbolAddress((void**)&pq,  g_q);
    cudaGetSymbolAddress((void**)&pk,  g_k);
    cudaGetSymbolAddress((void**)&pv,  g_v);
    cudaGetSymbolAddress((void**)&pxq, g_xq);
    cudaGetSymbolAddress((void**)&pxk, g_xk);
    cudaGetSymbolAddress((void**)&pxv, g_xv);
    cudaGetSymbolAddress((void**)&pwq, g_wq);
    cudaGetSymbolAddress((void**)&pwk, g_wk);
    cudaGetSymbolAddress((void**)&pwv, g_wv);

    // Pre-round inputs to rna-tf32 so later HMMA truncation is lossless.
    const int nX4 = (RR * DD) / 4;
    const int nW4 = (DD * DD) / 4;
    round_tf32_kernel<<<2048, 256>>>((const float4*)queries, (float4*)pxq, nX4);
    round_tf32_kernel<<<2048, 256>>>((const float4*)keys,    (float4*)pxk, nX4);
    round_tf32_kernel<<<2048, 256>>>((const float4*)values,  (float4*)pxv, nX4);
    round_tf32_kernel<<<256, 256>>>((const float4*)Wq, (float4*)pwq, nW4);
    round_tf32_kernel<<<256, 256>>>((const float4*)Wk, (float4*)pwk, nW4);
    round_tf32_kernel<<<256, 256>>>((const float4*)Wv, (float4*)pwv, nW4);

    cudaFuncSetAttribute(proj_mma_kernel,
                         cudaFuncAttributeMaxDynamicSharedMemorySize, PROJ_SMEM_BYTES);
    dim3 pGrid(DD / 64, RR / 128, 3);   // (8, 64, 3)
    proj_mma_kernel<<<pGrid, 128, PROJ_SMEM_BYTES>>>(
        pxq, pxk, pxv, pwq, pwk, pwv, bq, bk, bv, pq, pk, pv);

    cudaFuncSetAttribute(attn_mma_kernel,
                         cudaFuncAttributeMaxDynamicSharedMemorySize, ATTN_SMEM_BYTES);
    dim3 aGrid(NN / 128, HH, BB);       // (32, 8, 2)
    attn_mma_kernel<<<aGrid, 128, ATTN_SMEM_BYTES>>>(pq, pk, pv, out);
}

// round 10
// speedup vs baseline: 7.4085x; 1.5443x over previous
#include <cuda_runtime.h>
#include <cuda_fp16.h>
#include <math_constants.h>
#include <cstdint>

// Problem constants
#define BB   2
#define NN   4096
#define MM   4096
#define DD   512
#define HH   8
#define PP   64
#define RR   (BB * NN)

// ---------------- scratch ----------------
__device__ __half g_q[(size_t)RR * DD];
__device__ __half g_k[(size_t)RR * DD];
__device__ __half g_v[(size_t)RR * DD];
__device__ float  g_xq[(size_t)RR * DD];
__device__ float  g_xk[(size_t)RR * DD];
__device__ float  g_xv[(size_t)RR * DD];
__device__ float  g_wq[(size_t)DD * DD];
__device__ float  g_wk[(size_t)DD * DD];
__device__ float  g_wv[(size_t)DD * DD];

// ---------------- helpers ----------------
__device__ __forceinline__ uint32_t f2tf(float f) {
    uint32_t u;
    asm("cvt.rna.tf32.f32 %0, %1;" : "=r"(u) : "f"(f));
    return u;
}
__device__ __forceinline__ uint32_t smem_u32(const void* p) {
    uint32_t a;
    asm("{ .reg .u64 t; cvta.to.shared.u64 t, %1; cvt.u32.u64 %0, t; }" : "=r"(a) : "l"(p));
    return a;
}
#define CP_ASYNC16(dst_u32, src) \
    asm volatile("cp.async.cg.shared.global [%0], [%1], 16;" :: "r"(dst_u32), "l"(src))
#define CP_COMMIT() asm volatile("cp.async.commit_group;" ::: "memory")
#define CP_WAIT1()  asm volatile("cp.async.wait_group 1;" ::: "memory")
#define CP_WAIT0()  asm volatile("cp.async.wait_group 0;" ::: "memory")

// tf32: D(16x8) += A(16x8) @ B(8x8)
__device__ __forceinline__ void mma8(float c[4], const uint32_t a[4],
                                     uint32_t b0, uint32_t b1) {
    asm volatile(
        "mma.sync.aligned.m16n8k8.row.col.f32.tf32.tf32.f32 "
        "{%0,%1,%2,%3}, {%4,%5,%6,%7}, {%8,%9}, {%0,%1,%2,%3};\n"
        : "+f"(c[0]), "+f"(c[1]), "+f"(c[2]), "+f"(c[3])
        : "r"(a[0]), "r"(a[1]), "r"(a[2]), "r"(a[3]), "r"(b0), "r"(b1));
}
// fp16: D(16x8) += A(16x16) @ B(16x8), fp32 accum
__device__ __forceinline__ void mma16(float c[4], uint32_t a0, uint32_t a1,
                                      uint32_t a2, uint32_t a3,
                                      uint32_t b0, uint32_t b1) {
    asm volatile(
        "mma.sync.aligned.m16n8k16.row.col.f32.f16.f16.f32 "
        "{%0,%1,%2,%3}, {%4,%5,%6,%7}, {%8,%9}, {%0,%1,%2,%3};\n"
        : "+f"(c[0]), "+f"(c[1]), "+f"(c[2]), "+f"(c[3])
        : "r"(a0), "r"(a1), "r"(a2), "r"(a3), "r"(b0), "r"(b1));
}
__device__ __forceinline__ uint32_t packh2(float lo, float hi) {
    __half2 h = __floats2half2_rn(lo, hi);
    return *reinterpret_cast<uint32_t*>(&h);
}

// ================= Pre-round pass: rna-tf32 in gmem =================
__global__ __launch_bounds__(256) void round_tf32_kernel(
    const float4* __restrict__ src, float4* __restrict__ dst, int n4)
{
    int i = blockIdx.x * blockDim.x + threadIdx.x;
    int stride = gridDim.x * blockDim.x;
    for (; i < n4; i += stride) {
        float4 v = src[i];
        v.x = __uint_as_float(f2tf(v.x));
        v.y = __uint_as_float(f2tf(v.y));
        v.z = __uint_as_float(f2tf(v.z));
        v.w = __uint_as_float(f2tf(v.w));
        dst[i] = v;
    }
}

// ================= Projection GEMM via mma tf32, fp16 output =================
#define PXSTR 68
#define PWSTR 72
#define POFF_X0 0
#define POFF_X1 (128 * PXSTR)
#define POFF_W0 (2 * 128 * PXSTR)
#define POFF_W1 (2 * 128 * PXSTR + 64 * PWSTR)
#define PROJ_SMEM_BYTES ((2 * 128 * PXSTR + 2 * 64 * PWSTR) * 4)
#define NCH 8

__global__ __launch_bounds__(128) void proj_mma_kernel(
    const float* __restrict__ Xq, const float* __restrict__ Xk, const float* __restrict__ Xv,
    const float* __restrict__ Wq, const float* __restrict__ Wk, const float* __restrict__ Wv,
    const float* __restrict__ bq, const float* __restrict__ bk, const float* __restrict__ bv,
    __half* __restrict__ Yq, __half* __restrict__ Yk, __half* __restrict__ Yv)
{
    extern __shared__ uint32_t smw[];
    const uint32_t smbase = smem_u32(smw);

    const int z = blockIdx.z;
    const float* X    = z == 0 ? Xq : (z == 1 ? Xk : Xv);
    const float* W    = z == 0 ? Wq : (z == 1 ? Wk : Wv);
    const float* bias = z == 0 ? bq : (z == 1 ? bk : bv);
    __half*      Y    = z == 0 ? Yq : (z == 1 ? Yk : Yv);
    const float  sc   = z == 0 ? 0.125f : 1.0f;   // fold 1/sqrt(P) into Q

    const int tid  = threadIdx.x;
    const int lane = tid & 31;
    const int w    = tid >> 5;
    const int gid  = lane >> 2;
    const int tig  = lane & 3;
    const int rb   = blockIdx.y * 128;
    const int cb   = blockIdx.x * 64;

    const int ldr = tid >> 4;
    const int ldc = tid & 15;

    {
        const float* Xc = X + (size_t)rb * DD;
#pragma unroll
        for (int l = 0; l < 16; l++) {
            int row = ldr + l * 8;
            CP_ASYNC16(smbase + (uint32_t)(POFF_X0 + row * PXSTR + ldc * 4) * 4,
                       Xc + (size_t)row * DD + ldc * 4);
        }
        const float* Wc = W + cb;
#pragma unroll
        for (int l = 0; l < 8; l++) {
            int row = ldr + l * 8;
            CP_ASYNC16(smbase + (uint32_t)(POFF_W0 + row * PWSTR + ldc * 4) * 4,
                       Wc + (size_t)row * DD + ldc * 4);
        }
        CP_COMMIT();
    }

    float acc0[8][4], acc1[8][4];
#pragma unroll
    for (int nt = 0; nt < 8; nt++)
#pragma unroll
        for (int c = 0; c < 4; c++) { acc0[nt][c] = 0.0f; acc1[nt][c] = 0.0f; }

    for (int ch = 0; ch < NCH; ch++) {
        int cur = ch & 1;
        if (ch + 1 < NCH) {
            int nb = (ch + 1) & 1;
            const float* Xc = X + (size_t)rb * DD + (ch + 1) * 64;
#pragma unroll
            for (int l = 0; l < 16; l++) {
                int row = ldr + l * 8;
                CP_ASYNC16(smbase + (uint32_t)((nb ? POFF_X1 : POFF_X0) + row * PXSTR + ldc * 4) * 4,
                           Xc + (size_t)row * DD + ldc * 4);
            }
            const float* Wc = W + (size_t)((ch + 1) * 64) * DD + cb;
#pragma unroll
            for (int l = 0; l < 8; l++) {
                int row = ldr + l * 8;
                CP_ASYNC16(smbase + (uint32_t)((nb ? POFF_W1 : POFF_W0) + row * PWSTR + ldc * 4) * 4,
                           Wc + (size_t)row * DD + ldc * 4);
            }
            CP_COMMIT();
            CP_WAIT1();
        } else {
            CP_WAIT0();
        }
        __syncthreads();

        const uint32_t* sX = smw + (cur ? POFF_X1 : POFF_X0);
        const uint32_t* sW = smw + (cur ? POFF_W1 : POFF_W0);

#pragma unroll
        for (int ks = 0; ks < 8; ks++) {
            uint32_t a0[4], a1[4];
            const uint32_t* x0 = &sX[(w * 32 + gid) * PXSTR + ks * 8];
            a0[0] = x0[tig];               a0[2] = x0[tig + 4];
            a0[1] = x0[8 * PXSTR + tig];   a0[3] = x0[8 * PXSTR + tig + 4];
            a1[0] = x0[16 * PXSTR + tig];  a1[2] = x0[16 * PXSTR + tig + 4];
            a1[1] = x0[24 * PXSTR + tig];  a1[3] = x0[24 * PXSTR + tig + 4];
            const uint32_t* wr0 = &sW[(ks * 8 + tig) * PWSTR];
            const uint32_t* wr1 = wr0 + 4 * PWSTR;
#pragma unroll
            for (int nt = 0; nt < 8; nt++) {
                uint32_t b0 = wr0[nt * 8 + gid];
                uint32_t b1 = wr1[nt * 8 + gid];
                mma8(acc0[nt], a0, b0, b1);
                mma8(acc1[nt], a1, b0, b1);
            }
        }
        __syncthreads();
    }

    // epilogue: bias, scale, fp16 round, half2 store
    const int r0 = rb + w * 32 + gid;
#pragma unroll
    for (int nt = 0; nt < 8; nt++) {
        int col = cb + nt * 8 + 2 * tig;
        float2 bv2 = *(const float2*)(bias + col);
        uint32_t o;
        o = packh2((acc0[nt][0] + bv2.x) * sc, (acc0[nt][1] + bv2.y) * sc);
        *(uint32_t*)(Y + (size_t)r0 * DD + col) = o;
        o = packh2((acc0[nt][2] + bv2.x) * sc, (acc0[nt][3] + bv2.y) * sc);
        *(uint32_t*)(Y + (size_t)(r0 + 8) * DD + col) = o;
        o = packh2((acc1[nt][0] + bv2.x) * sc, (acc1[nt][1] + bv2.y) * sc);
        *(uint32_t*)(Y + (size_t)(r0 + 16) * DD + col) = o;
        o = packh2((acc1[nt][2] + bv2.x) * sc, (acc1[nt][3] + bv2.y) * sc);
        *(uint32_t*)(Y + (size_t)(r0 + 24) * DD + col) = o;
    }
}

// ================= Flash attention: fp16 m16n8k16, P register-resident =====
// CTA = 128 thr (4 warps), 128 q rows (32/warp), KV tile 64 keys dbl-buffered.
// fp16 A-fragment of PV == QK C-fragment layout -> P never touches smem.
#define KT    64
#define NTIL  (MM / KT)
#define KSTRH 72   // halfs; 144B row stride -> conflict-free frag reads

__shared__ __half sKh[2][KT * KSTRH];
__shared__ __half sVh[2][KT * KSTRH];

// Online-softmax update for one 16-row group.
#define SOFTMAX2(sarr, i0, i1, mvar, lvar, accarr) do {                       \
    float _mx = fmaxf(sarr[0][i0], sarr[0][i1]);                              \
    _Pragma("unroll")                                                         \
    for (int _nt = 1; _nt < 8; _nt++)                                         \
        _mx = fmaxf(_mx, fmaxf(sarr[_nt][i0], sarr[_nt][i1]));                \
    _mx = fmaxf(_mx, __shfl_xor_sync(0xffffffffu, _mx, 1));                   \
    _mx = fmaxf(_mx, __shfl_xor_sync(0xffffffffu, _mx, 2));                   \
    float _mn = fmaxf(mvar, _mx);                                             \
    float _corr = __expf(mvar - _mn);                                         \
    mvar = _mn;                                                               \
    float _sum = 0.0f;                                                        \
    _Pragma("unroll")                                                         \
    for (int _nt = 0; _nt < 8; _nt++) {                                       \
        sarr[_nt][i0] = __expf(sarr[_nt][i0] - _mn);                          \
        sarr[_nt][i1] = __expf(sarr[_nt][i1] - _mn);                          \
        _sum += sarr[_nt][i0] + sarr[_nt][i1];                                \
    }                                                                         \
    _sum += __shfl_xor_sync(0xffffffffu, _sum, 1);                            \
    _sum += __shfl_xor_sync(0xffffffffu, _sum, 2);                            \
    lvar = lvar * _corr + _sum;                                               \
    _Pragma("unroll")                                                         \
    for (int _nt = 0; _nt < 8; _nt++) {                                       \
        accarr[_nt][i0] *= _corr;                                             \
        accarr[_nt][i1] *= _corr;                                             \
    }                                                                         \
} while (0)

__global__ void __launch_bounds__(128, 2) attn_mma_kernel(
    const __half* __restrict__ Q, const __half* __restrict__ K,
    const __half* __restrict__ V, float* __restrict__ O)
{
    const int tid  = threadIdx.x;
    const int lane = tid & 31;
    const int w    = tid >> 5;
    const int gid  = lane >> 2;
    const int tig  = lane & 3;

    const int b  = blockIdx.z;
    const int h  = blockIdx.y;
    const int q0 = blockIdx.x * 128;

    const __half* Qb = Q + ((size_t)(b * NN + q0 + w * 32)) * DD + h * PP;
    const __half* Kb = K + ((size_t)b * MM) * DD + h * PP;
    const __half* Vb = V + ((size_t)b * MM) * DD + h * PP;

    const uint32_t kb0 = smem_u32(&sKh[0][0]);
    const uint32_t kb1 = smem_u32(&sKh[1][0]);
    const uint32_t vb0 = smem_u32(&sVh[0][0]);
    const uint32_t vb1 = smem_u32(&sVh[1][0]);

    // prefetch KV tile 0 into buf 0 (rows of 64 halfs = 8 chunks of 16B)
#pragma unroll
    for (int i = 0; i < 4; i++) {
        int idx = tid + 128 * i;      // 0..511
        int row = idx >> 3, c = idx & 7;
        CP_ASYNC16(kb0 + (uint32_t)(row * KSTRH + c * 8) * 2,
                   Kb + (size_t)row * DD + c * 8);
        CP_ASYNC16(vb0 + (uint32_t)(row * KSTRH + c * 8) * 2,
                   Vb + (size_t)row * DD + c * 8);
    }
    CP_COMMIT();

    // Q fragments (fp16, pre-scaled): 2 m-tiles x 4 k-steps x 4 regs
    uint32_t qa0[4][4], qa1[4][4];
#pragma unroll
    for (int ko = 0; ko < 4; ko++) {
        int d0 = 16 * ko + 2 * tig;
        qa0[ko][0] = *(const uint32_t*)(Qb + (size_t)gid * DD + d0);
        qa0[ko][1] = *(const uint32_t*)(Qb + (size_t)(gid + 8) * DD + d0);
        qa0[ko][2] = *(const uint32_t*)(Qb + (size_t)gid * DD + d0 + 8);
        qa0[ko][3] = *(const uint32_t*)(Qb + (size_t)(gid + 8) * DD + d0 + 8);
        qa1[ko][0] = *(const uint32_t*)(Qb + (size_t)(gid + 16) * DD + d0);
        qa1[ko][1] = *(const uint32_t*)(Qb + (size_t)(gid + 24) * DD + d0);
        qa1[ko][2] = *(const uint32_t*)(Qb + (size_t)(gid + 16) * DD + d0 + 8);
        qa1[ko][3] = *(const uint32_t*)(Qb + (size_t)(gid + 24) * DD + d0 + 8);
    }

    float acc0[8][4], acc1[8][4];
#pragma unroll
    for (int nt = 0; nt < 8; nt++)
#pragma unroll
        for (int c = 0; c < 4; c++) { acc0[nt][c] = 0.0f; acc1[nt][c] = 0.0f; }
    float m00 = -CUDART_INF_F, m01 = -CUDART_INF_F;
    float m10 = -CUDART_INF_F, m11 = -CUDART_INF_F;
    float l00 = 0.0f, l01 = 0.0f, l10 = 0.0f, l11 = 0.0f;

    for (int t = 0; t < NTIL; t++) {
        int cur = t & 1;
        if (t + 1 < NTIL) {
            uint32_t kb = (t + 1) & 1 ? kb1 : kb0;
            uint32_t vb = (t + 1) & 1 ? vb1 : vb0;
            const __half* Ks = Kb + (size_t)(t + 1) * KT * DD;
            const __half* Vs = Vb + (size_t)(t + 1) * KT * DD;
#pragma unroll
            for (int i = 0; i < 4; i++) {
                int idx = tid + 128 * i;
                int row = idx >> 3, c = idx & 7;
                CP_ASYNC16(kb + (uint32_t)(row * KSTRH + c * 8) * 2,
                           Ks + (size_t)row * DD + c * 8);
                CP_ASYNC16(vb + (uint32_t)(row * KSTRH + c * 8) * 2,
                           Vs + (size_t)row * DD + c * 8);
            }
            CP_COMMIT();
            CP_WAIT1();
        } else {
            CP_WAIT0();
        }
        __syncthreads();

        const __half* sK = &sKh[cur][0];
        const __half* sV = &sVh[cur][0];

        // --- QK^T: S_w[32 x 64] (b-loads shared by both m-tiles) ---
        float s0[8][4], s1[8][4];
#pragma unroll
        for (int nt = 0; nt < 8; nt++) {
            s0[nt][0] = s0[nt][1] = s0[nt][2] = s0[nt][3] = 0.0f;
            s1[nt][0] = s1[nt][1] = s1[nt][2] = s1[nt][3] = 0.0f;
            const __half* krow = sK + (nt * 8 + gid) * KSTRH;
#pragma unroll
            for (int ko = 0; ko < 4; ko++) {
                uint32_t b0 = *(const uint32_t*)(krow + 16 * ko + 2 * tig);
                uint32_t b1 = *(const uint32_t*)(krow + 16 * ko + 2 * tig + 8);
                mma16(s0[nt], qa0[ko][0], qa0[ko][1], qa0[ko][2], qa0[ko][3], b0, b1);
                mma16(s1[nt], qa1[ko][0], qa1[ko][1], qa1[ko][2], qa1[ko][3], b0, b1);
            }
        }

        // --- online softmax (4 groups of 16 rows) ---
        SOFTMAX2(s0, 0, 1, m00, l00, acc0);
        SOFTMAX2(s0, 2, 3, m01, l01, acc0);
        SOFTMAX2(s1, 0, 1, m10, l10, acc1);
        SOFTMAX2(s1, 2, 3, m11, l11, acc1);

        // --- PV: acc += P @ V. P fragments come straight from registers. ---
#pragma unroll
        for (int ko = 0; ko < 4; ko++) {
            uint32_t a0 = packh2(s0[2*ko][0],   s0[2*ko][1]);
            uint32_t a1 = packh2(s0[2*ko][2],   s0[2*ko][3]);
            uint32_t a2 = packh2(s0[2*ko+1][0], s0[2*ko+1][1]);
            uint32_t a3 = packh2(s0[2*ko+1][2], s0[2*ko+1][3]);
            uint32_t c0 = packh2(s1[2*ko][0],   s1[2*ko][1]);
            uint32_t c1 = packh2(s1[2*ko][2],   s1[2*ko][3]);
            uint32_t c2 = packh2(s1[2*ko+1][0], s1[2*ko+1][1]);
            uint32_t c3 = packh2(s1[2*ko+1][2], s1[2*ko+1][3]);
            const __half* vk = sV + (16 * ko + 2 * tig) * KSTRH;
#pragma unroll
            for (int nt = 0; nt < 8; nt++) {
                int d = nt * 8 + gid;
                // B frag: key-adjacent pairs (cross-row in V) -> u16 pack
                uint32_t u0 = *(const unsigned short*)(vk + d);
                uint32_t u1 = *(const unsigned short*)(vk + KSTRH + d);
                uint32_t u2 = *(const unsigned short*)(vk + 8 * KSTRH + d);
                uint32_t u3 = *(const unsigned short*)(vk + 9 * KSTRH + d);
                uint32_t b0 = u0 | (u1 << 16);
                uint32_t b1 = u2 | (u3 << 16);
                mma16(acc0[nt], a0, a1, a2, a3, b0, b1);
                mma16(acc1[nt], c0, c1, c2, c3, b0, b1);
            }
        }
        __syncthreads();   // all warps done with this K/V buffer before re-prefetch
    }

    // --- normalize & store ---
    float i00 = 1.0f / l00, i01 = 1.0f / l01, i10 = 1.0f / l10, i11 = 1.0f / l11;
    float* Ob = O + ((size_t)(b * NN + q0 + w * 32)) * DD + h * PP;
#pragma unroll
    for (int nt = 0; nt < 8; nt++) {
        int col = nt * 8 + 2 * tig;
        *(float2*)(Ob + (size_t)gid * DD + col) =
            make_float2(acc0[nt][0] * i00, acc0[nt][1] * i00);
        *(float2*)(Ob + (size_t)(gid + 8) * DD + col) =
            make_float2(acc0[nt][2] * i01, acc0[nt][3] * i01);
        *(float2*)(Ob + (size_t)(gid + 16) * DD + col) =
            make_float2(acc1[nt][0] * i10, acc1[nt][1] * i10);
        *(float2*)(Ob + (size_t)(gid + 24) * DD + col) =
            make_float2(acc1[nt][2] * i11, acc1[nt][3] * i11);
    }
}

// ---------------- launch ----------------
extern "C" void kernel_launch(void* const* d_in, const int* in_sizes, int n_in,
                              void* d_out, int out_size)
{
    const float* queries = (const float*)d_in[0];
    const float* keys    = (const float*)d_in[1];
    const float* values  = (const float*)d_in[2];
    const float* Wq      = (const float*)d_in[3];
    const float* bq      = (const float*)d_in[4];
    const float* Wk      = (const float*)d_in[5];
    const float* bk      = (const float*)d_in[6];
    const float* Wv      = (const float*)d_in[7];
    const float* bv      = (const float*)d_in[8];
    float* out = (float*)d_out;

    __half *pq, *pk, *pv;
    float *pxq, *pxk, *pxv, *pwq, *pwk, *pwv;
    cudaGetSymbolAddress((void**)&pq,  g_q);
    cudaGetSymbolAddress((void**)&pk,  g_k);
    cudaGetSymbolAddress((void**)&pv,  g_v);
    cudaGetSymbolAddress((void**)&pxq, g_xq);
    cudaGetSymbolAddress((void**)&pxk, g_xk);
    cudaGetSymbolAddress((void**)&pxv, g_xv);
    cudaGetSymbolAddress((void**)&pwq, g_wq);
    cudaGetSymbolAddress((void**)&pwk, g_wk);
    cudaGetSymbolAddress((void**)&pwv, g_wv);

    // Pre-round X/W to rna-tf32 so projection HMMA truncation is lossless.
    const int nX4 = (RR * DD) / 4;
    const int nW4 = (DD * DD) / 4;
    round_tf32_kernel<<<2048, 256>>>((const float4*)queries, (float4*)pxq, nX4);
    round_tf32_kernel<<<2048, 256>>>((const float4*)keys,    (float4*)pxk, nX4);
    round_tf32_kernel<<<2048, 256>>>((const float4*)values,  (float4*)pxv, nX4);
    round_tf32_kernel<<<256, 256>>>((const float4*)Wq, (float4*)pwq, nW4);
    round_tf32_kernel<<<256, 256>>>((const float4*)Wk, (float4*)pwk, nW4);
    round_tf32_kernel<<<256, 256>>>((const float4*)Wv, (float4*)pwv, nW4);

    cudaFuncSetAttribute(proj_mma_kernel,
                         cudaFuncAttributeMaxDynamicSharedMemorySize, PROJ_SMEM_BYTES);
    dim3 pGrid(DD / 64, RR / 128, 3);   // (8, 64, 3)
    proj_mma_kernel<<<pGrid, 128, PROJ_SMEM_BYTES>>>(
        pxq, pxk, pxv, pwq, pwk, pwv, bq, bk, bv, pq, pk, pv);

    dim3 aGrid(NN / 128, HH, BB);       // (32, 8, 2)
    attn_mma_kernel<<<aGrid, 128>>>(pq, pk, pv, out);
}

// round 13
// speedup vs baseline: 8.5043x; 1.1479x over previous
#include <cuda_runtime.h>
#include <cuda_fp16.h>
#include <math_constants.h>
#include <cstdint>

// Problem constants
#define BB   2
#define NN   4096
#define MM   4096
#define DD   512
#define HH   8
#define PP   64
#define RR   (BB * NN)

// ---------------- scratch (fp16) ----------------
__device__ __half g_q[(size_t)RR * DD];
__device__ __half g_k[(size_t)RR * DD];
__device__ __half g_v[(size_t)RR * DD];
__device__ __half g_xq[(size_t)RR * DD];
__device__ __half g_xk[(size_t)RR * DD];
__device__ __half g_xv[(size_t)RR * DD];
__device__ __half g_wqt[(size_t)DD * DD];   // transposed: Wt[n][k]
__device__ __half g_wkt[(size_t)DD * DD];
__device__ __half g_wvt[(size_t)DD * DD];

// ---------------- helpers ----------------
__device__ __forceinline__ uint32_t smem_u32(const void* p) {
    uint32_t a;
    asm("{ .reg .u64 t; cvta.to.shared.u64 t, %1; cvt.u32.u64 %0, t; }" : "=r"(a) : "l"(p));
    return a;
}
#define CP_ASYNC16(dst_u32, src) \
    asm volatile("cp.async.cg.shared.global [%0], [%1], 16;" :: "r"(dst_u32), "l"(src))
#define CP_COMMIT() asm volatile("cp.async.commit_group;" ::: "memory")
#define CP_WAIT1()  asm volatile("cp.async.wait_group 1;" ::: "memory")
#define CP_WAIT0()  asm volatile("cp.async.wait_group 0;" ::: "memory")

// fp16: D(16x8) += A(16x16) @ B(16x8), fp32 accum
__device__ __forceinline__ void mma16(float c[4], uint32_t a0, uint32_t a1,
                                      uint32_t a2, uint32_t a3,
                                      uint32_t b0, uint32_t b1) {
    asm volatile(
        "mma.sync.aligned.m16n8k16.row.col.f32.f16.f16.f32 "
        "{%0,%1,%2,%3}, {%4,%5,%6,%7}, {%8,%9}, {%0,%1,%2,%3};\n"
        : "+f"(c[0]), "+f"(c[1]), "+f"(c[2]), "+f"(c[3])
        : "r"(a0), "r"(a1), "r"(a2), "r"(a3), "r"(b0), "r"(b1));
}
__device__ __forceinline__ uint32_t packh2(float lo, float hi) {
    __half2 h = __floats2half2_rn(lo, hi);
    return *reinterpret_cast<uint32_t*>(&h);
}

// ================= Convert passes =================
// fp32 -> fp16 elementwise (for X inputs)
__global__ __launch_bounds__(256) void f2h_kernel(
    const float4* __restrict__ src, __half* __restrict__ dst, int n4)
{
    int i = blockIdx.x * blockDim.x + threadIdx.x;
    int stride = gridDim.x * blockDim.x;
    for (; i < n4; i += stride) {
        float4 v = src[i];
        uint2 o;
        o.x = packh2(v.x, v.y);
        o.y = packh2(v.z, v.w);
        *(uint2*)(dst + (size_t)i * 4) = o;
    }
}
// W[k][n] fp32 -> Wt[n][k] fp16, 32x32 smem tiles
__global__ __launch_bounds__(256) void wt_h_kernel(
    const float* __restrict__ W, __half* __restrict__ Wt)
{
    __shared__ float t[32][33];
    const int tx = threadIdx.x, ty = threadIdx.y;   // block (32,8)
    const int bx = blockIdx.x * 32;   // n base
    const int by = blockIdx.y * 32;   // k base
#pragma unroll
    for (int j = 0; j < 32; j += 8)
        t[ty + j][tx] = W[(size_t)(by + ty + j) * DD + bx + tx];
    __syncthreads();
#pragma unroll
    for (int j = 0; j < 32; j += 8)
        Wt[(size_t)(bx + ty + j) * DD + by + tx] = __float2half(t[tx][ty + j]);
}

// ================= Projection GEMM via mma fp16 =================
// Y[8192,512] = X @ W + b; X fp16 row-major, W pre-transposed fp16 (Wt[n][k]).
// CTA = 128 thr (4 warps), tile M=128 (32 rows/warp), N=64, K-chunks 64,
// cp.async double-buffered. One launch, z selects proj.
#define XSTRH 72   // halfs, 144B rows -> conflict-free frag reads
#define POFF_X0 0
#define POFF_X1 (128 * XSTRH)
#define POFF_W0 (2 * 128 * XSTRH)
#define POFF_W1 (2 * 128 * XSTRH + 64 * XSTRH)
#define PROJ_SMEM_BYTES ((2 * 128 * XSTRH + 2 * 64 * XSTRH) * 2)   // 55296 B
#define NCH 8

__global__ __launch_bounds__(128) void proj_mma_kernel(
    const __half* __restrict__ Xq, const __half* __restrict__ Xk, const __half* __restrict__ Xv,
    const __half* __restrict__ Wqt, const __half* __restrict__ Wkt, const __half* __restrict__ Wvt,
    const float* __restrict__ bq, const float* __restrict__ bk, const float* __restrict__ bv,
    __half* __restrict__ Yq, __half* __restrict__ Yk, __half* __restrict__ Yv)
{
    extern __shared__ __half smh[];
    const uint32_t smbase = smem_u32(smh);

    const int z = blockIdx.z;
    const __half* X    = z == 0 ? Xq : (z == 1 ? Xk : Xv);
    const __half* Wt   = z == 0 ? Wqt : (z == 1 ? Wkt : Wvt);
    const float*  bias = z == 0 ? bq : (z == 1 ? bk : bv);
    __half*       Y    = z == 0 ? Yq : (z == 1 ? Yk : Yv);
    // Q gets 1/sqrt(P) * log2(e) folded in (softmax done base-2 downstream).
    const float   sc   = z == 0 ? 0.125f * 1.4426950408889634f : 1.0f;

    const int tid  = threadIdx.x;
    const int lane = tid & 31;
    const int w    = tid >> 5;
    const int gid  = lane >> 2;
    const int tig  = lane & 3;
    const int rb   = blockIdx.y * 128;
    const int cb   = blockIdx.x * 64;

    // prefetch chunk 0: X tile 128x64 halfs (1024 16B-chunks), Wt tile 64x64 (512)
    {
        const __half* Xc = X + (size_t)rb * DD;
#pragma unroll
        for (int i = 0; i < 8; i++) {
            int idx = tid + 128 * i;
            int row = idx >> 3, c = idx & 7;
            CP_ASYNC16(smbase + (uint32_t)(POFF_X0 + row * XSTRH + c * 8) * 2,
                       Xc + (size_t)row * DD + c * 8);
        }
        const __half* Wc = Wt + (size_t)cb * DD;
#pragma unroll
        for (int i = 0; i < 4; i++) {
            int idx = tid + 128 * i;
            int row = idx >> 3, c = idx & 7;
            CP_ASYNC16(smbase + (uint32_t)(POFF_W0 + row * XSTRH + c * 8) * 2,
                       Wc + (size_t)row * DD + c * 8);
        }
        CP_COMMIT();
    }

    float acc0[8][4], acc1[8][4];
#pragma unroll
    for (int nt = 0; nt < 8; nt++)
#pragma unroll
        for (int c = 0; c < 4; c++) { acc0[nt][c] = 0.0f; acc1[nt][c] = 0.0f; }

    for (int ch = 0; ch < NCH; ch++) {
        int cur = ch & 1;
        if (ch + 1 < NCH) {
            int nb = (ch + 1) & 1;
            const __half* Xc = X + (size_t)rb * DD + (ch + 1) * 64;
#pragma unroll
            for (int i = 0; i < 8; i++) {
                int idx = tid + 128 * i;
                int row = idx >> 3, c = idx & 7;
                CP_ASYNC16(smbase + (uint32_t)((nb ? POFF_X1 : POFF_X0) + row * XSTRH + c * 8) * 2,
                           Xc + (size_t)row * DD + c * 8);
            }
            const __half* Wc = Wt + (size_t)cb * DD + (ch + 1) * 64;
#pragma unroll
            for (int i = 0; i < 4; i++) {
                int idx = tid + 128 * i;
                int row = idx >> 3, c = idx & 7;
                CP_ASYNC16(smbase + (uint32_t)((nb ? POFF_W1 : POFF_W0) + row * XSTRH + c * 8) * 2,
                           Wc + (size_t)row * DD + c * 8);
            }
            CP_COMMIT();
            CP_WAIT1();
        } else {
            CP_WAIT0();
        }
        __syncthreads();

        const __half* sX = smh + (cur ? POFF_X1 : POFF_X0);
        const __half* sW = smh + (cur ? POFF_W1 : POFF_W0);

#pragma unroll
        for (int ko = 0; ko < 4; ko++) {
            const __half* x0 = sX + (w * 32 + gid) * XSTRH + 16 * ko + 2 * tig;
            uint32_t a00 = *(const uint32_t*)x0;
            uint32_t a01 = *(const uint32_t*)(x0 + 8 * XSTRH);
            uint32_t a02 = *(const uint32_t*)(x0 + 8);
            uint32_t a03 = *(const uint32_t*)(x0 + 8 * XSTRH + 8);
            uint32_t a10 = *(const uint32_t*)(x0 + 16 * XSTRH);
            uint32_t a11 = *(const uint32_t*)(x0 + 24 * XSTRH);
            uint32_t a12 = *(const uint32_t*)(x0 + 16 * XSTRH + 8);
            uint32_t a13 = *(const uint32_t*)(x0 + 24 * XSTRH + 8);
#pragma unroll
            for (int nt = 0; nt < 8; nt++) {
                const __half* wrow = sW + (nt * 8 + gid) * XSTRH + 16 * ko + 2 * tig;
                uint32_t b0 = *(const uint32_t*)wrow;
                uint32_t b1 = *(const uint32_t*)(wrow + 8);
                mma16(acc0[nt], a00, a01, a02, a03, b0, b1);
                mma16(acc1[nt], a10, a11, a12, a13, b0, b1);
            }
        }
        __syncthreads();
    }

    // epilogue: bias, scale, fp16 round, half2 store
    const int r0 = rb + w * 32 + gid;
#pragma unroll
    for (int nt = 0; nt < 8; nt++) {
        int col = cb + nt * 8 + 2 * tig;
        float2 bv2 = *(const float2*)(bias + col);
        uint32_t o;
        o = packh2((acc0[nt][0] + bv2.x) * sc, (acc0[nt][1] + bv2.y) * sc);
        *(uint32_t*)(Y + (size_t)r0 * DD + col) = o;
        o = packh2((acc0[nt][2] + bv2.x) * sc, (acc0[nt][3] + bv2.y) * sc);
        *(uint32_t*)(Y + (size_t)(r0 + 8) * DD + col) = o;
        o = packh2((acc1[nt][0] + bv2.x) * sc, (acc1[nt][1] + bv2.y) * sc);
        *(uint32_t*)(Y + (size_t)(r0 + 16) * DD + col) = o;
        o = packh2((acc1[nt][2] + bv2.x) * sc, (acc1[nt][3] + bv2.y) * sc);
        *(uint32_t*)(Y + (size_t)(r0 + 24) * DD + col) = o;
    }
}

// ================= Flash attention: fp16 m16n8k16, P register-resident =====
// CTA = 128 thr (4 warps), 128 q rows (32/warp), KV tile 64 keys dbl-buffered.
// Scores arrive pre-scaled by log2(e)/sqrt(P): softmax runs in base 2 (exp2f).
#define KT    64
#define NTIL  (MM / KT)
#define KSTRH 72

__shared__ __half sKh[2][KT * KSTRH];
__shared__ __half sVh[2][KT * KSTRH];

// Online-softmax (base 2) update for one 16-row group.
#define SOFTMAX2(sarr, i0, i1, mvar, lvar, accarr) do {                       \
    float _mx = fmaxf(sarr[0][i0], sarr[0][i1]);                              \
    _Pragma("unroll")                                                         \
    for (int _nt = 1; _nt < 8; _nt++)                                         \
        _mx = fmaxf(_mx, fmaxf(sarr[_nt][i0], sarr[_nt][i1]));                \
    _mx = fmaxf(_mx, __shfl_xor_sync(0xffffffffu, _mx, 1));                   \
    _mx = fmaxf(_mx, __shfl_xor_sync(0xffffffffu, _mx, 2));                   \
    float _mn = fmaxf(mvar, _mx);                                             \
    float _corr = exp2f(mvar - _mn);                                          \
    mvar = _mn;                                                               \
    float _sum = 0.0f;                                                        \
    _Pragma("unroll")                                                         \
    for (int _nt = 0; _nt < 8; _nt++) {                                       \
        sarr[_nt][i0] = exp2f(sarr[_nt][i0] - _mn);                           \
        sarr[_nt][i1] = exp2f(sarr[_nt][i1] - _mn);                           \
        _sum += sarr[_nt][i0] + sarr[_nt][i1];                                \
    }                                                                         \
    _sum += __shfl_xor_sync(0xffffffffu, _sum, 1);                            \
    _sum += __shfl_xor_sync(0xffffffffu, _sum, 2);                            \
    lvar = lvar * _corr + _sum;                                               \
    _Pragma("unroll")                                                         \
    for (int _nt = 0; _nt < 8; _nt++) {                                       \
        accarr[_nt][i0] *= _corr;                                             \
        accarr[_nt][i1] *= _corr;                                             \
    }                                                                         \
} while (0)

__global__ void __launch_bounds__(128, 2) attn_mma_kernel(
    const __half* __restrict__ Q, const __half* __restrict__ K,
    const __half* __restrict__ V, float* __restrict__ O)
{
    const int tid  = threadIdx.x;
    const int lane = tid & 31;
    const int w    = tid >> 5;
    const int gid  = lane >> 2;
    const int tig  = lane & 3;

    const int b  = blockIdx.z;
    const int h  = blockIdx.y;
    const int q0 = blockIdx.x * 128;

    const __half* Qb = Q + ((size_t)(b * NN + q0 + w * 32)) * DD + h * PP;
    const __half* Kb = K + ((size_t)b * MM) * DD + h * PP;
    const __half* Vb = V + ((size_t)b * MM) * DD + h * PP;

    const uint32_t kb0 = smem_u32(&sKh[0][0]);
    const uint32_t kb1 = smem_u32(&sKh[1][0]);
    const uint32_t vb0 = smem_u32(&sVh[0][0]);
    const uint32_t vb1 = smem_u32(&sVh[1][0]);

#pragma unroll
    for (int i = 0; i < 4; i++) {
        int idx = tid + 128 * i;
        int row = idx >> 3, c = idx & 7;
        CP_ASYNC16(kb0 + (uint32_t)(row * KSTRH + c * 8) * 2,
                   Kb + (size_t)row * DD + c * 8);
        CP_ASYNC16(vb0 + (uint32_t)(row * KSTRH + c * 8) * 2,
                   Vb + (size_t)row * DD + c * 8);
    }
    CP_COMMIT();

    uint32_t qa0[4][4], qa1[4][4];
#pragma unroll
    for (int ko = 0; ko < 4; ko++) {
        int d0 = 16 * ko + 2 * tig;
        qa0[ko][0] = *(const uint32_t*)(Qb + (size_t)gid * DD + d0);
        qa0[ko][1] = *(const uint32_t*)(Qb + (size_t)(gid + 8) * DD + d0);
        qa0[ko][2] = *(const uint32_t*)(Qb + (size_t)gid * DD + d0 + 8);
        qa0[ko][3] = *(const uint32_t*)(Qb + (size_t)(gid + 8) * DD + d0 + 8);
        qa1[ko][0] = *(const uint32_t*)(Qb + (size_t)(gid + 16) * DD + d0);
        qa1[ko][1] = *(const uint32_t*)(Qb + (size_t)(gid + 24) * DD + d0);
        qa1[ko][2] = *(const uint32_t*)(Qb + (size_t)(gid + 16) * DD + d0 + 8);
        qa1[ko][3] = *(const uint32_t*)(Qb + (size_t)(gid + 24) * DD + d0 + 8);
    }

    float acc0[8][4], acc1[8][4];
#pragma unroll
    for (int nt = 0; nt < 8; nt++)
#pragma unroll
        for (int c = 0; c < 4; c++) { acc0[nt][c] = 0.0f; acc1[nt][c] = 0.0f; }
    float m00 = -CUDART_INF_F, m01 = -CUDART_INF_F;
    float m10 = -CUDART_INF_F, m11 = -CUDART_INF_F;
    float l00 = 0.0f, l01 = 0.0f, l10 = 0.0f, l11 = 0.0f;

    for (int t = 0; t < NTIL; t++) {
        int cur = t & 1;
        if (t + 1 < NTIL) {
            uint32_t kb = (t + 1) & 1 ? kb1 : kb0;
            uint32_t vb = (t + 1) & 1 ? vb1 : vb0;
            const __half* Ks = Kb + (size_t)(t + 1) * KT * DD;
            const __half* Vs = Vb + (size_t)(t + 1) * KT * DD;
#pragma unroll
            for (int i = 0; i < 4; i++) {
                int idx = tid + 128 * i;
                int row = idx >> 3, c = idx & 7;
                CP_ASYNC16(kb + (uint32_t)(row * KSTRH + c * 8) * 2,
                           Ks + (size_t)row * DD + c * 8);
                CP_ASYNC16(vb + (uint32_t)(row * KSTRH + c * 8) * 2,
                           Vs + (size_t)row * DD + c * 8);
            }
            CP_COMMIT();
            CP_WAIT1();
        } else {
            CP_WAIT0();
        }
        __syncthreads();

        const __half* sK = &sKh[cur][0];
        const __half* sV = &sVh[cur][0];

        // --- QK^T ---
        float s0[8][4], s1[8][4];
#pragma unroll
        for (int nt = 0; nt < 8; nt++) {
            s0[nt][0] = s0[nt][1] = s0[nt][2] = s0[nt][3] = 0.0f;
            s1[nt][0] = s1[nt][1] = s1[nt][2] = s1[nt][3] = 0.0f;
            const __half* krow = sK + (nt * 8 + gid) * KSTRH;
#pragma unroll
            for (int ko = 0; ko < 4; ko++) {
                uint32_t b0 = *(const uint32_t*)(krow + 16 * ko + 2 * tig);
                uint32_t b1 = *(const uint32_t*)(krow + 16 * ko + 2 * tig + 8);
                mma16(s0[nt], qa0[ko][0], qa0[ko][1], qa0[ko][2], qa0[ko][3], b0, b1);
                mma16(s1[nt], qa1[ko][0], qa1[ko][1], qa1[ko][2], qa1[ko][3], b0, b1);
            }
        }

        // --- online softmax (base 2) ---
        SOFTMAX2(s0, 0, 1, m00, l00, acc0);
        SOFTMAX2(s0, 2, 3, m01, l01, acc0);
        SOFTMAX2(s1, 0, 1, m10, l10, acc1);
        SOFTMAX2(s1, 2, 3, m11, l11, acc1);

        // --- PV: P fragments straight from registers ---
#pragma unroll
        for (int ko = 0; ko < 4; ko++) {
            uint32_t a0 = packh2(s0[2*ko][0],   s0[2*ko][1]);
            uint32_t a1 = packh2(s0[2*ko][2],   s0[2*ko][3]);
            uint32_t a2 = packh2(s0[2*ko+1][0], s0[2*ko+1][1]);
            uint32_t a3 = packh2(s0[2*ko+1][2], s0[2*ko+1][3]);
            uint32_t c0 = packh2(s1[2*ko][0],   s1[2*ko][1]);
            uint32_t c1 = packh2(s1[2*ko][2],   s1[2*ko][3]);
            uint32_t c2 = packh2(s1[2*ko+1][0], s1[2*ko+1][1]);
            uint32_t c3 = packh2(s1[2*ko+1][2], s1[2*ko+1][3]);
            const __half* vk = sV + (16 * ko + 2 * tig) * KSTRH;
#pragma unroll
            for (int nt = 0; nt < 8; nt++) {
                int d = nt * 8 + gid;
                uint32_t u0 = *(const unsigned short*)(vk + d);
                uint32_t u1 = *(const unsigned short*)(vk + KSTRH + d);
                uint32_t u2 = *(const unsigned short*)(vk + 8 * KSTRH + d);
                uint32_t u3 = *(const unsigned short*)(vk + 9 * KSTRH + d);
                uint32_t b0 = u0 | (u1 << 16);
                uint32_t b1 = u2 | (u3 << 16);
                mma16(acc0[nt], a0, a1, a2, a3, b0, b1);
                mma16(acc1[nt], c0, c1, c2, c3, b0, b1);
            }
        }
        __syncthreads();
    }

    // --- normalize & store ---
    float i00 = 1.0f / l00, i01 = 1.0f / l01, i10 = 1.0f / l10, i11 = 1.0f / l11;
    float* Ob = O + ((size_t)(b * NN + q0 + w * 32)) * DD + h * PP;
#pragma unroll
    for (int nt = 0; nt < 8; nt++) {
        int col = nt * 8 + 2 * tig;
        *(float2*)(Ob + (size_t)gid * DD + col) =
            make_float2(acc0[nt][0] * i00, acc0[nt][1] * i00);
        *(float2*)(Ob + (size_t)(gid + 8) * DD + col) =
            make_float2(acc0[nt][2] * i01, acc0[nt][3] * i01);
        *(float2*)(Ob + (size_t)(gid + 16) * DD + col) =
            make_float2(acc1[nt][0] * i10, acc1[nt][1] * i10);
        *(float2*)(Ob + (size_t)(gid + 24) * DD + col) =
            make_float2(acc1[nt][2] * i11, acc1[nt][3] * i11);
    }
}

// ---------------- launch ----------------
extern "C" void kernel_launch(void* const* d_in, const int* in_sizes, int n_in,
                              void* d_out, int out_size)
{
    const float* queries = (const float*)d_in[0];
    const float* keys    = (const float*)d_in[1];
    const float* values  = (const float*)d_in[2];
    const float* Wq      = (const float*)d_in[3];
    const float* bq      = (const float*)d_in[4];
    const float* Wk      = (const float*)d_in[5];
    const float* bk      = (const float*)d_in[6];
    const float* Wv      = (const float*)d_in[7];
    const float* bv      = (const float*)d_in[8];
    float* out = (float*)d_out;

    __half *pq, *pk, *pv, *pxq, *pxk, *pxv, *pwq, *pwk, *pwv;
    cudaGetSymbolAddress((void**)&pq,  g_q);
    cudaGetSymbolAddress((void**)&pk,  g_k);
    cudaGetSymbolAddress((void**)&pv,  g_v);
    cudaGetSymbolAddress((void**)&pxq, g_xq);
    cudaGetSymbolAddress((void**)&pxk, g_xk);
    cudaGetSymbolAddress((void**)&pxv, g_xv);
    cudaGetSymbolAddress((void**)&pwq, g_wqt);
    cudaGetSymbolAddress((void**)&pwk, g_wkt);
    cudaGetSymbolAddress((void**)&pwv, g_wvt);

    // Convert inputs to fp16 (X elementwise; W transposed).
    const int nX4 = (RR * DD) / 4;
    f2h_kernel<<<2048, 256>>>((const float4*)queries, pxq, nX4);
    f2h_kernel<<<2048, 256>>>((const float4*)keys,    pxk, nX4);
    f2h_kernel<<<2048, 256>>>((const float4*)values,  pxv, nX4);
    dim3 tBlock(32, 8), tGrid(DD / 32, DD / 32);
    wt_h_kernel<<<tGrid, tBlock>>>(Wq, pwq);
    wt_h_kernel<<<tGrid, tBlock>>>(Wk, pwk);
    wt_h_kernel<<<tGrid, tBlock>>>(Wv, pwv);

    cudaFuncSetAttribute(proj_mma_kernel,
                         cudaFuncAttributeMaxDynamicSharedMemorySize, PROJ_SMEM_BYTES);
    dim3 pGrid(DD / 64, RR / 128, 3);   // (8, 64, 3)
    proj_mma_kernel<<<pGrid, 128, PROJ_SMEM_BYTES>>>(
        pxq, pxk, pxv, pwq, pwk, pwv, bq, bk, bv, pq, pk, pv);

    dim3 aGrid(NN / 128, HH, BB);       // (32, 8, 2)
    attn_mma_kernel<<<aGrid, 128>>>(pq, pk, pv, out);
}

// round 14
// speedup vs baseline: 8.9617x; 1.0538x over previous
#include <cuda_runtime.h>
#include <cuda_fp16.h>
#include <math_constants.h>
#include <cstdint>

// Problem constants
#define BB   2
#define NN   4096
#define MM   4096
#define DD   512
#define HH   8
#define PP   64
#define RR   (BB * NN)

// ---------------- scratch (fp16) ----------------
__device__ __half g_q[(size_t)RR * DD];
__device__ __half g_k[(size_t)RR * DD];
__device__ __half g_vt[(size_t)RR * DD];    // V transposed: [b][h][p][m]
__device__ __half g_xq[(size_t)RR * DD];
__device__ __half g_xk[(size_t)RR * DD];
__device__ __half g_xv[(size_t)RR * DD];
__device__ __half g_wqt[(size_t)DD * DD];   // W transposed: Wt[n][k]
__device__ __half g_wkt[(size_t)DD * DD];
__device__ __half g_wvt[(size_t)DD * DD];

// ---------------- helpers ----------------
__device__ __forceinline__ uint32_t smem_u32(const void* p) {
    uint32_t a;
    asm("{ .reg .u64 t; cvta.to.shared.u64 t, %1; cvt.u32.u64 %0, t; }" : "=r"(a) : "l"(p));
    return a;
}
#define CP_ASYNC16(dst_u32, src) \
    asm volatile("cp.async.cg.shared.global [%0], [%1], 16;" :: "r"(dst_u32), "l"(src))
#define CP_COMMIT() asm volatile("cp.async.commit_group;" ::: "memory")
#define CP_WAIT1()  asm volatile("cp.async.wait_group 1;" ::: "memory")
#define CP_WAIT0()  asm volatile("cp.async.wait_group 0;" ::: "memory")

// fp16: D(16x8) += A(16x16) @ B(16x8), fp32 accum
__device__ __forceinline__ void mma16(float c[4], uint32_t a0, uint32_t a1,
                                      uint32_t a2, uint32_t a3,
                                      uint32_t b0, uint32_t b1) {
    asm volatile(
        "mma.sync.aligned.m16n8k16.row.col.f32.f16.f16.f32 "
        "{%0,%1,%2,%3}, {%4,%5,%6,%7}, {%8,%9}, {%0,%1,%2,%3};\n"
        : "+f"(c[0]), "+f"(c[1]), "+f"(c[2]), "+f"(c[3])
        : "r"(a0), "r"(a1), "r"(a2), "r"(a3), "r"(b0), "r"(b1));
}
__device__ __forceinline__ uint32_t packh2(float lo, float hi) {
    __half2 h = __floats2half2_rn(lo, hi);
    return *reinterpret_cast<uint32_t*>(&h);
}

// ================= Convert passes =================
__global__ __launch_bounds__(256) void f2h_kernel(
    const float4* __restrict__ src, __half* __restrict__ dst, int n4)
{
    int i = blockIdx.x * blockDim.x + threadIdx.x;
    int stride = gridDim.x * blockDim.x;
    for (; i < n4; i += stride) {
        float4 v = src[i];
        uint2 o;
        o.x = packh2(v.x, v.y);
        o.y = packh2(v.z, v.w);
        *(uint2*)(dst + (size_t)i * 4) = o;
    }
}
// W[k][n] fp32 -> Wt[n][k] fp16, 32x32 smem tiles
__global__ __launch_bounds__(256) void wt_h_kernel(
    const float* __restrict__ W, __half* __restrict__ Wt)
{
    __shared__ float t[32][33];
    const int tx = threadIdx.x, ty = threadIdx.y;   // block (32,8)
    const int bx = blockIdx.x * 32;   // n base
    const int by = blockIdx.y * 32;   // k base
#pragma unroll
    for (int j = 0; j < 32; j += 8)
        t[ty + j][tx] = W[(size_t)(by + ty + j) * DD + bx + tx];
    __syncthreads();
#pragma unroll
    for (int j = 0; j < 32; j += 8)
        Wt[(size_t)(bx + ty + j) * DD + by + tx] = __float2half(t[tx][ty + j]);
}

// ================= Projection GEMM via mma fp16 =================
// Y[8192,512] = X @ W + b; X fp16 row-major, W pre-transposed fp16 (Wt[n][k]).
// z==2 (V) writes its output TRANSPOSED: Vt[((b*8+h)*64+p)*M + m] so the
// attention PV B-fragments become contiguous 32-bit smem loads.
#define XSTRH 72   // halfs, 144B rows -> conflict-free frag reads
#define POFF_X0 0
#define POFF_X1 (128 * XSTRH)
#define POFF_W0 (2 * 128 * XSTRH)
#define POFF_W1 (2 * 128 * XSTRH + 64 * XSTRH)
#define PROJ_SMEM_BYTES ((2 * 128 * XSTRH + 2 * 64 * XSTRH) * 2)   // 55296 B
#define NCH 8

__global__ __launch_bounds__(128) void proj_mma_kernel(
    const __half* __restrict__ Xq, const __half* __restrict__ Xk, const __half* __restrict__ Xv,
    const __half* __restrict__ Wqt, const __half* __restrict__ Wkt, const __half* __restrict__ Wvt,
    const float* __restrict__ bq, const float* __restrict__ bk, const float* __restrict__ bv,
    __half* __restrict__ Yq, __half* __restrict__ Yk, __half* __restrict__ Yv)
{
    extern __shared__ __half smh[];
    const uint32_t smbase = smem_u32(smh);

    const int z = blockIdx.z;
    const __half* X    = z == 0 ? Xq : (z == 1 ? Xk : Xv);
    const __half* Wt   = z == 0 ? Wqt : (z == 1 ? Wkt : Wvt);
    const float*  bias = z == 0 ? bq : (z == 1 ? bk : bv);
    __half*       Y    = z == 0 ? Yq : (z == 1 ? Yk : Yv);
    // Q gets 1/sqrt(P) * log2(e) folded in (softmax done base-2 downstream).
    const float   sc   = z == 0 ? 0.125f * 1.4426950408889634f : 1.0f;

    const int tid  = threadIdx.x;
    const int lane = tid & 31;
    const int w    = tid >> 5;
    const int gid  = lane >> 2;
    const int tig  = lane & 3;
    const int rb   = blockIdx.y * 128;
    const int cb   = blockIdx.x * 64;

    // prefetch chunk 0
    {
        const __half* Xc = X + (size_t)rb * DD;
#pragma unroll
        for (int i = 0; i < 8; i++) {
            int idx = tid + 128 * i;
            int row = idx >> 3, c = idx & 7;
            CP_ASYNC16(smbase + (uint32_t)(POFF_X0 + row * XSTRH + c * 8) * 2,
                       Xc + (size_t)row * DD + c * 8);
        }
        const __half* Wc = Wt + (size_t)cb * DD;
#pragma unroll
        for (int i = 0; i < 4; i++) {
            int idx = tid + 128 * i;
            int row = idx >> 3, c = idx & 7;
            CP_ASYNC16(smbase + (uint32_t)(POFF_W0 + row * XSTRH + c * 8) * 2,
                       Wc + (size_t)row * DD + c * 8);
        }
        CP_COMMIT();
    }

    float acc0[8][4], acc1[8][4];
#pragma unroll
    for (int nt = 0; nt < 8; nt++)
#pragma unroll
        for (int c = 0; c < 4; c++) { acc0[nt][c] = 0.0f; acc1[nt][c] = 0.0f; }

    for (int ch = 0; ch < NCH; ch++) {
        int cur = ch & 1;
        if (ch + 1 < NCH) {
            int nb = (ch + 1) & 1;
            const __half* Xc = X + (size_t)rb * DD + (ch + 1) * 64;
#pragma unroll
            for (int i = 0; i < 8; i++) {
                int idx = tid + 128 * i;
                int row = idx >> 3, c = idx & 7;
                CP_ASYNC16(smbase + (uint32_t)((nb ? POFF_X1 : POFF_X0) + row * XSTRH + c * 8) * 2,
                           Xc + (size_t)row * DD + c * 8);
            }
            const __half* Wc = Wt + (size_t)cb * DD + (ch + 1) * 64;
#pragma unroll
            for (int i = 0; i < 4; i++) {
                int idx = tid + 128 * i;
                int row = idx >> 3, c = idx & 7;
                CP_ASYNC16(smbase + (uint32_t)((nb ? POFF_W1 : POFF_W0) + row * XSTRH + c * 8) * 2,
                           Wc + (size_t)row * DD + c * 8);
            }
            CP_COMMIT();
            CP_WAIT1();
        } else {
            CP_WAIT0();
        }
        __syncthreads();

        const __half* sX = smh + (cur ? POFF_X1 : POFF_X0);
        const __half* sW = smh + (cur ? POFF_W1 : POFF_W0);

#pragma unroll
        for (int ko = 0; ko < 4; ko++) {
            const __half* x0 = sX + (w * 32 + gid) * XSTRH + 16 * ko + 2 * tig;
            uint32_t a00 = *(const uint32_t*)x0;
            uint32_t a01 = *(const uint32_t*)(x0 + 8 * XSTRH);
            uint32_t a02 = *(const uint32_t*)(x0 + 8);
            uint32_t a03 = *(const uint32_t*)(x0 + 8 * XSTRH + 8);
            uint32_t a10 = *(const uint32_t*)(x0 + 16 * XSTRH);
            uint32_t a11 = *(const uint32_t*)(x0 + 24 * XSTRH);
            uint32_t a12 = *(const uint32_t*)(x0 + 16 * XSTRH + 8);
            uint32_t a13 = *(const uint32_t*)(x0 + 24 * XSTRH + 8);
#pragma unroll
            for (int nt = 0; nt < 8; nt++) {
                const __half* wrow = sW + (nt * 8 + gid) * XSTRH + 16 * ko + 2 * tig;
                uint32_t b0 = *(const uint32_t*)wrow;
                uint32_t b1 = *(const uint32_t*)(wrow + 8);
                mma16(acc0[nt], a00, a01, a02, a03, b0, b1);
                mma16(acc1[nt], a10, a11, a12, a13, b0, b1);
            }
        }
        __syncthreads();
    }

    // epilogue
    const int r0 = rb + w * 32 + gid;
    if (z == 2) {
        // Transposed store for V: Vt[((b*8+h)*64+p)*MM + m]
        const int b_ = rb >> 12;               // batch (rows 128-aligned, never straddle)
        const int h_ = cb >> 6;                // head
        __half* Vtb = Y + ((size_t)(b_ * HH + h_) * PP) * MM;
        const int m0 = r0 & (NN - 1);
#pragma unroll
        for (int nt = 0; nt < 8; nt++) {
            int p = nt * 8 + 2 * tig;          // head-dim index (cb&63 == 0)
            int col = cb + p;
            float2 bv2 = *(const float2*)(bias + col);
            Vtb[(size_t)p * MM + m0]            = __float2half(acc0[nt][0] + bv2.x);
            Vtb[(size_t)(p + 1) * MM + m0]      = __float2half(acc0[nt][1] + bv2.y);
            Vtb[(size_t)p * MM + m0 + 8]        = __float2half(acc0[nt][2] + bv2.x);
            Vtb[(size_t)(p + 1) * MM + m0 + 8]  = __float2half(acc0[nt][3] + bv2.y);
            Vtb[(size_t)p * MM + m0 + 16]       = __float2half(acc1[nt][0] + bv2.x);
            Vtb[(size_t)(p + 1) * MM + m0 + 16] = __float2half(acc1[nt][1] + bv2.y);
            Vtb[(size_t)p * MM + m0 + 24]       = __float2half(acc1[nt][2] + bv2.x);
            Vtb[(size_t)(p + 1) * MM + m0 + 24] = __float2half(acc1[nt][3] + bv2.y);
        }
    } else {
#pragma unroll
        for (int nt = 0; nt < 8; nt++) {
            int col = cb + nt * 8 + 2 * tig;
            float2 bv2 = *(const float2*)(bias + col);
            uint32_t o;
            o = packh2((acc0[nt][0] + bv2.x) * sc, (acc0[nt][1] + bv2.y) * sc);
            *(uint32_t*)(Y + (size_t)r0 * DD + col) = o;
            o = packh2((acc0[nt][2] + bv2.x) * sc, (acc0[nt][3] + bv2.y) * sc);
            *(uint32_t*)(Y + (size_t)(r0 + 8) * DD + col) = o;
            o = packh2((acc1[nt][0] + bv2.x) * sc, (acc1[nt][1] + bv2.y) * sc);
            *(uint32_t*)(Y + (size_t)(r0 + 16) * DD + col) = o;
            o = packh2((acc1[nt][2] + bv2.x) * sc, (acc1[nt][3] + bv2.y) * sc);
            *(uint32_t*)(Y + (size_t)(r0 + 24) * DD + col) = o;
        }
    }
}

// ================= Flash attention: fp16 m16n8k16, Vt d-major =====
// CTA = 128 thr (4 warps), 128 q rows (32/warp), KV tile 64 keys dbl-buffered.
// V stored transposed in gmem/smem (d-major): PV B-frags are single LDS.32.
#define KT    64
#define NTIL  (MM / KT)
#define KSTRH 72

__shared__ __half sKh[2][KT * KSTRH];
__shared__ __half sVt[2][PP * KSTRH];   // [d][key], 64 x 72

// Online-softmax (base 2) update for one 16-row group.
#define SOFTMAX2(sarr, i0, i1, mvar, lvar, accarr) do {                       \
    float _mx = fmaxf(sarr[0][i0], sarr[0][i1]);                              \
    _Pragma("unroll")                                                         \
    for (int _nt = 1; _nt < 8; _nt++)                                         \
        _mx = fmaxf(_mx, fmaxf(sarr[_nt][i0], sarr[_nt][i1]));                \
    _mx = fmaxf(_mx, __shfl_xor_sync(0xffffffffu, _mx, 1));                   \
    _mx = fmaxf(_mx, __shfl_xor_sync(0xffffffffu, _mx, 2));                   \
    float _mn = fmaxf(mvar, _mx);                                             \
    float _corr = exp2f(mvar - _mn);                                          \
    mvar = _mn;                                                               \
    float _sum = 0.0f;                                                        \
    _Pragma("unroll")                                                         \
    for (int _nt = 0; _nt < 8; _nt++) {                                       \
        sarr[_nt][i0] = exp2f(sarr[_nt][i0] - _mn);                           \
        sarr[_nt][i1] = exp2f(sarr[_nt][i1] - _mn);                           \
        _sum += sarr[_nt][i0] + sarr[_nt][i1];                                \
    }                                                                         \
    _sum += __shfl_xor_sync(0xffffffffu, _sum, 1);                            \
    _sum += __shfl_xor_sync(0xffffffffu, _sum, 2);                            \
    lvar = lvar * _corr + _sum;                                               \
    _Pragma("unroll")                                                         \
    for (int _nt = 0; _nt < 8; _nt++) {                                       \
        accarr[_nt][i0] *= _corr;                                             \
        accarr[_nt][i1] *= _corr;                                             \
    }                                                                         \
} while (0)

__global__ void __launch_bounds__(128, 2) attn_mma_kernel(
    const __half* __restrict__ Q, const __half* __restrict__ K,
    const __half* __restrict__ Vt, float* __restrict__ O)
{
    const int tid  = threadIdx.x;
    const int lane = tid & 31;
    const int w    = tid >> 5;
    const int gid  = lane >> 2;
    const int tig  = lane & 3;

    const int b  = blockIdx.z;
    const int h  = blockIdx.y;
    const int q0 = blockIdx.x * 128;

    const __half* Qb  = Q + ((size_t)(b * NN + q0 + w * 32)) * DD + h * PP;
    const __half* Kb  = K + ((size_t)b * MM) * DD + h * PP;
    const __half* Vtb = Vt + ((size_t)(b * HH + h) * PP) * MM;   // [p][m]

    const uint32_t kb0 = smem_u32(&sKh[0][0]);
    const uint32_t kb1 = smem_u32(&sKh[1][0]);
    const uint32_t vb0 = smem_u32(&sVt[0][0]);
    const uint32_t vb1 = smem_u32(&sVt[1][0]);

    // prefetch KV tile 0: K rows (stride DD), Vt rows (stride MM)
#pragma unroll
    for (int i = 0; i < 4; i++) {
        int idx = tid + 128 * i;
        int row = idx >> 3, c = idx & 7;
        CP_ASYNC16(kb0 + (uint32_t)(row * KSTRH + c * 8) * 2,
                   Kb + (size_t)row * DD + c * 8);
        CP_ASYNC16(vb0 + (uint32_t)(row * KSTRH + c * 8) * 2,
                   Vtb + (size_t)row * MM + c * 8);
    }
    CP_COMMIT();

    uint32_t qa0[4][4], qa1[4][4];
#pragma unroll
    for (int ko = 0; ko < 4; ko++) {
        int d0 = 16 * ko + 2 * tig;
        qa0[ko][0] = *(const uint32_t*)(Qb + (size_t)gid * DD + d0);
        qa0[ko][1] = *(const uint32_t*)(Qb + (size_t)(gid + 8) * DD + d0);
        qa0[ko][2] = *(const uint32_t*)(Qb + (size_t)gid * DD + d0 + 8);
        qa0[ko][3] = *(const uint32_t*)(Qb + (size_t)(gid + 8) * DD + d0 + 8);
        qa1[ko][0] = *(const uint32_t*)(Qb + (size_t)(gid + 16) * DD + d0);
        qa1[ko][1] = *(const uint32_t*)(Qb + (size_t)(gid + 24) * DD + d0);
        qa1[ko][2] = *(const uint32_t*)(Qb + (size_t)(gid + 16) * DD + d0 + 8);
        qa1[ko][3] = *(const uint32_t*)(Qb + (size_t)(gid + 24) * DD + d0 + 8);
    }

    float acc0[8][4], acc1[8][4];
#pragma unroll
    for (int nt = 0; nt < 8; nt++)
#pragma unroll
        for (int c = 0; c < 4; c++) { acc0[nt][c] = 0.0f; acc1[nt][c] = 0.0f; }
    float m00 = -CUDART_INF_F, m01 = -CUDART_INF_F;
    float m10 = -CUDART_INF_F, m11 = -CUDART_INF_F;
    float l00 = 0.0f, l01 = 0.0f, l10 = 0.0f, l11 = 0.0f;

    for (int t = 0; t < NTIL; t++) {
        int cur = t & 1;
        if (t + 1 < NTIL) {
            uint32_t kb = (t + 1) & 1 ? kb1 : kb0;
            uint32_t vb = (t + 1) & 1 ? vb1 : vb0;
            const __half* Ks  = Kb + (size_t)(t + 1) * KT * DD;
            const __half* Vts = Vtb + (t + 1) * KT;
#pragma unroll
            for (int i = 0; i < 4; i++) {
                int idx = tid + 128 * i;
                int row = idx >> 3, c = idx & 7;
                CP_ASYNC16(kb + (uint32_t)(row * KSTRH + c * 8) * 2,
                           Ks + (size_t)row * DD + c * 8);
                CP_ASYNC16(vb + (uint32_t)(row * KSTRH + c * 8) * 2,
                           Vts + (size_t)row * MM + c * 8);
            }
            CP_COMMIT();
            CP_WAIT1();
        } else {
            CP_WAIT0();
        }
        __syncthreads();

        const __half* sK = &sKh[cur][0];
        const __half* sV = &sVt[cur][0];

        // --- QK^T ---
        float s0[8][4], s1[8][4];
#pragma unroll
        for (int nt = 0; nt < 8; nt++) {
            s0[nt][0] = s0[nt][1] = s0[nt][2] = s0[nt][3] = 0.0f;
            s1[nt][0] = s1[nt][1] = s1[nt][2] = s1[nt][3] = 0.0f;
            const __half* krow = sK + (nt * 8 + gid) * KSTRH;
#pragma unroll
            for (int ko = 0; ko < 4; ko++) {
                uint32_t b0 = *(const uint32_t*)(krow + 16 * ko + 2 * tig);
                uint32_t b1 = *(const uint32_t*)(krow + 16 * ko + 2 * tig + 8);
                mma16(s0[nt], qa0[ko][0], qa0[ko][1], qa0[ko][2], qa0[ko][3], b0, b1);
                mma16(s1[nt], qa1[ko][0], qa1[ko][1], qa1[ko][2], qa1[ko][3], b0, b1);
            }
        }

        // --- online softmax (base 2) ---
        SOFTMAX2(s0, 0, 1, m00, l00, acc0);
        SOFTMAX2(s0, 2, 3, m01, l01, acc0);
        SOFTMAX2(s1, 0, 1, m10, l10, acc1);
        SOFTMAX2(s1, 2, 3, m11, l11, acc1);

        // --- PV: P from registers; V B-frags contiguous in d-major sVt ---
#pragma unroll
        for (int ko = 0; ko < 4; ko++) {
            uint32_t a0 = packh2(s0[2*ko][0],   s0[2*ko][1]);
            uint32_t a1 = packh2(s0[2*ko][2],   s0[2*ko][3]);
            uint32_t a2 = packh2(s0[2*ko+1][0], s0[2*ko+1][1]);
            uint32_t a3 = packh2(s0[2*ko+1][2], s0[2*ko+1][3]);
            uint32_t c0 = packh2(s1[2*ko][0],   s1[2*ko][1]);
            uint32_t c1 = packh2(s1[2*ko][2],   s1[2*ko][3]);
            uint32_t c2 = packh2(s1[2*ko+1][0], s1[2*ko+1][1]);
            uint32_t c3 = packh2(s1[2*ko+1][2], s1[2*ko+1][3]);
#pragma unroll
            for (int nt = 0; nt < 8; nt++) {
                const __half* vrow = sV + (nt * 8 + gid) * KSTRH + 16 * ko + 2 * tig;
                uint32_t b0 = *(const uint32_t*)vrow;        // {V[k],V[k+1]} at dim d
                uint32_t b1 = *(const uint32_t*)(vrow + 8);  // {V[k+8],V[k+9]}
                mma16(acc0[nt], a0, a1, a2, a3, b0, b1);
                mma16(acc1[nt], c0, c1, c2, c3, b0, b1);
            }
        }
        __syncthreads();
    }

    // --- normalize & store ---
    float i00 = 1.0f / l00, i01 = 1.0f / l01, i10 = 1.0f / l10, i11 = 1.0f / l11;
    float* Ob = O + ((size_t)(b * NN + q0 + w * 32)) * DD + h * PP;
#pragma unroll
    for (int nt = 0; nt < 8; nt++) {
        int col = nt * 8 + 2 * tig;
        *(float2*)(Ob + (size_t)gid * DD + col) =
            make_float2(acc0[nt][0] * i00, acc0[nt][1] * i00);
        *(float2*)(Ob + (size_t)(gid + 8) * DD + col) =
            make_float2(acc0[nt][2] * i01, acc0[nt][3] * i01);
        *(float2*)(Ob + (size_t)(gid + 16) * DD + col) =
            make_float2(acc1[nt][0] * i10, acc1[nt][1] * i10);
        *(float2*)(Ob + (size_t)(gid + 24) * DD + col) =
            make_float2(acc1[nt][2] * i11, acc1[nt][3] * i11);
    }
}

// ---------------- launch ----------------
extern "C" void kernel_launch(void* const* d_in, const int* in_sizes, int n_in,
                              void* d_out, int out_size)
{
    const float* queries = (const float*)d_in[0];
    const float* keys    = (const float*)d_in[1];
    const float* values  = (const float*)d_in[2];
    const float* Wq      = (const float*)d_in[3];
    const float* bq      = (const float*)d_in[4];
    const float* Wk      = (const float*)d_in[5];
    const float* bk      = (const float*)d_in[6];
    const float* Wv      = (const float*)d_in[7];
    const float* bv      = (const float*)d_in[8];
    float* out = (float*)d_out;

    __half *pq, *pk, *pvt, *pxq, *pxk, *pxv, *pwq, *pwk, *pwv;
    cudaGetSymbolAddress((void**)&pq,  g_q);
    cudaGetSymbolAddress((void**)&pk,  g_k);
    cudaGetSymbolAddress((void**)&pvt, g_vt);
    cudaGetSymbolAddress((void**)&pxq, g_xq);
    cudaGetSymbolAddress((void**)&pxk, g_xk);
    cudaGetSymbolAddress((void**)&pxv, g_xv);
    cudaGetSymbolAddress((void**)&pwq, g_wqt);
    cudaGetSymbolAddress((void**)&pwk, g_wkt);
    cudaGetSymbolAddress((void**)&pwv, g_wvt);

    // Convert inputs to fp16 (X elementwise; W transposed).
    const int nX4 = (RR * DD) / 4;
    f2h_kernel<<<2048, 256>>>((const float4*)queries, pxq, nX4);
    f2h_kernel<<<2048, 256>>>((const float4*)keys,    pxk, nX4);
    f2h_kernel<<<2048, 256>>>((const float4*)values,  pxv, nX4);
    dim3 tBlock(32, 8), tGrid(DD / 32, DD / 32);
    wt_h_kernel<<<tGrid, tBlock>>>(Wq, pwq);
    wt_h_kernel<<<tGrid, tBlock>>>(Wk, pwk);
    wt_h_kernel<<<tGrid, tBlock>>>(Wv, pwv);

    cudaFuncSetAttribute(proj_mma_kernel,
                         cudaFuncAttributeMaxDynamicSharedMemorySize, PROJ_SMEM_BYTES);
    dim3 pGrid(DD / 64, RR / 128, 3);   // (8, 64, 3)
    proj_mma_kernel<<<pGrid, 128, PROJ_SMEM_BYTES>>>(
        pxq, pxk, pxv, pwq, pwk, pwv, bq, bk, bv, pq, pk, pvt);

    dim3 aGrid(NN / 128, HH, BB);       // (32, 8, 2)
    attn_mma_kernel<<<aGrid, 128>>>(pq, pk, pvt, out);
}

// round 15
// speedup vs baseline: 9.4731x; 1.0571x over previous
#include <cuda_runtime.h>
#include <cuda_fp16.h>
#include <math_constants.h>
#include <cstdint>

// Problem constants
#define BB   2
#define NN   4096
#define MM   4096
#define DD   512
#define HH   8
#define PP   64
#define RR   (BB * NN)

// ---------------- scratch (fp16) ----------------
__device__ __half g_q[(size_t)RR * DD];
__device__ __half g_k[(size_t)RR * DD];
__device__ __half g_vt[(size_t)RR * DD];    // V transposed: [b][h][p][m]
__device__ __half g_xq[(size_t)RR * DD];
__device__ __half g_xk[(size_t)RR * DD];
__device__ __half g_xv[(size_t)RR * DD];
__device__ __half g_wqt[(size_t)DD * DD];   // W transposed: Wt[n][k]
__device__ __half g_wkt[(size_t)DD * DD];
__device__ __half g_wvt[(size_t)DD * DD];

// ---------------- helpers ----------------
__device__ __forceinline__ uint32_t smem_u32(const void* p) {
    uint32_t a;
    asm("{ .reg .u64 t; cvta.to.shared.u64 t, %1; cvt.u32.u64 %0, t; }" : "=r"(a) : "l"(p));
    return a;
}
#define CP_ASYNC16(dst_u32, src) \
    asm volatile("cp.async.cg.shared.global [%0], [%1], 16;" :: "r"(dst_u32), "l"(src))
#define CP_COMMIT() asm volatile("cp.async.commit_group;" ::: "memory")
#define CP_WAIT1()  asm volatile("cp.async.wait_group 1;" ::: "memory")
#define CP_WAIT0()  asm volatile("cp.async.wait_group 0;" ::: "memory")

// fp16: D(16x8) += A(16x16) @ B(16x8), fp32 accum
__device__ __forceinline__ void mma16(float c[4], uint32_t a0, uint32_t a1,
                                      uint32_t a2, uint32_t a3,
                                      uint32_t b0, uint32_t b1) {
    asm volatile(
        "mma.sync.aligned.m16n8k16.row.col.f32.f16.f16.f32 "
        "{%0,%1,%2,%3}, {%4,%5,%6,%7}, {%8,%9}, {%0,%1,%2,%3};\n"
        : "+f"(c[0]), "+f"(c[1]), "+f"(c[2]), "+f"(c[3])
        : "r"(a0), "r"(a1), "r"(a2), "r"(a3), "r"(b0), "r"(b1));
}
__device__ __forceinline__ uint32_t packh2(float lo, float hi) {
    __half2 h = __floats2half2_rn(lo, hi);
    return *reinterpret_cast<uint32_t*>(&h);
}

// ================= Convert passes (fused over z) =================
__global__ __launch_bounds__(256) void f2h3_kernel(
    const float4* __restrict__ s0, const float4* __restrict__ s1,
    const float4* __restrict__ s2,
    __half* __restrict__ d0, __half* __restrict__ d1, __half* __restrict__ d2,
    int n4)
{
    const int z = blockIdx.z;
    const float4* src = z == 0 ? s0 : (z == 1 ? s1 : s2);
    __half*       dst = z == 0 ? d0 : (z == 1 ? d1 : d2);
    int i = blockIdx.x * blockDim.x + threadIdx.x;
    int stride = gridDim.x * blockDim.x;
    for (; i < n4; i += stride) {
        float4 v = src[i];
        uint2 o;
        o.x = packh2(v.x, v.y);
        o.y = packh2(v.z, v.w);
        *(uint2*)(dst + (size_t)i * 4) = o;
    }
}
// W[k][n] fp32 -> Wt[n][k] fp16, 32x32 smem tiles, z selects matrix
__global__ __launch_bounds__(256) void wt_h3_kernel(
    const float* __restrict__ W0, const float* __restrict__ W1,
    const float* __restrict__ W2,
    __half* __restrict__ T0, __half* __restrict__ T1, __half* __restrict__ T2)
{
    const int z = blockIdx.z;
    const float* W  = z == 0 ? W0 : (z == 1 ? W1 : W2);
    __half*      Wt = z == 0 ? T0 : (z == 1 ? T1 : T2);
    __shared__ float t[32][33];
    const int tx = threadIdx.x, ty = threadIdx.y;   // block (32,8)
    const int bx = blockIdx.x * 32;   // n base
    const int by = blockIdx.y * 32;   // k base
#pragma unroll
    for (int j = 0; j < 32; j += 8)
        t[ty + j][tx] = W[(size_t)(by + ty + j) * DD + bx + tx];
    __syncthreads();
#pragma unroll
    for (int j = 0; j < 32; j += 8)
        Wt[(size_t)(bx + ty + j) * DD + by + tx] = __float2half(t[tx][ty + j]);
}

// ================= Projection GEMM via mma fp16 =================
// Y[8192,512] = X @ W + b; tile M=128 x N=128, 256 thr (8 warps):
// warp w -> rows (w&3)*32, cols (w>>2)*64. K-chunks 64, cp.async dbl-buffered.
// X re-read factor drops 8 -> 4 vs the N=64 version.
// z==2 (V) writes output TRANSPOSED: Vt[((b*8+h)*64+p)*M + m].
#define PSTR 72    // halfs, 144B rows
#define POFF_X0 0
#define POFF_X1 (128 * PSTR)
#define POFF_W0 (2 * 128 * PSTR)
#define POFF_W1 (3 * 128 * PSTR)
#define PROJ_SMEM_BYTES (4 * 128 * PSTR * 2)   // 73728 B
#define NCH 8

__global__ __launch_bounds__(256) void proj_mma_kernel(
    const __half* __restrict__ Xq, const __half* __restrict__ Xk, const __half* __restrict__ Xv,
    const __half* __restrict__ Wqt, const __half* __restrict__ Wkt, const __half* __restrict__ Wvt,
    const float* __restrict__ bq, const float* __restrict__ bk, const float* __restrict__ bv,
    __half* __restrict__ Yq, __half* __restrict__ Yk, __half* __restrict__ Yv)
{
    extern __shared__ __half smh[];
    const uint32_t smbase = smem_u32(smh);

    const int z = blockIdx.z;
    const __half* X    = z == 0 ? Xq : (z == 1 ? Xk : Xv);
    const __half* Wt   = z == 0 ? Wqt : (z == 1 ? Wkt : Wvt);
    const float*  bias = z == 0 ? bq : (z == 1 ? bk : bv);
    __half*       Y    = z == 0 ? Yq : (z == 1 ? Yk : Yv);
    // Q gets 1/sqrt(P) * log2(e) folded in (softmax done base-2 downstream).
    const float   sc   = z == 0 ? 0.125f * 1.4426950408889634f : 1.0f;

    const int tid  = threadIdx.x;
    const int lane = tid & 31;
    const int w    = tid >> 5;      // 0..7
    const int wr   = w & 3;         // row block
    const int wc   = w >> 2;        // col block
    const int gid  = lane >> 2;
    const int tig  = lane & 3;
    const int rb   = blockIdx.y * 128;
    const int cb   = blockIdx.x * 128;

    // prefetch chunk 0: X 128x64 halfs, W 128x64 halfs (each 1024 16B-chunks)
    {
        const __half* Xc = X + (size_t)rb * DD;
        const __half* Wc = Wt + (size_t)cb * DD;
#pragma unroll
        for (int i = 0; i < 4; i++) {
            int idx = tid + 256 * i;
            int row = idx >> 3, c = idx & 7;
            CP_ASYNC16(smbase + (uint32_t)(POFF_X0 + row * PSTR + c * 8) * 2,
                       Xc + (size_t)row * DD + c * 8);
            CP_ASYNC16(smbase + (uint32_t)(POFF_W0 + row * PSTR + c * 8) * 2,
                       Wc + (size_t)row * DD + c * 8);
        }
        CP_COMMIT();
    }

    float acc0[8][4], acc1[8][4];
#pragma unroll
    for (int nt = 0; nt < 8; nt++)
#pragma unroll
        for (int c = 0; c < 4; c++) { acc0[nt][c] = 0.0f; acc1[nt][c] = 0.0f; }

    for (int ch = 0; ch < NCH; ch++) {
        int cur = ch & 1;
        if (ch + 1 < NCH) {
            int nb = (ch + 1) & 1;
            const __half* Xc = X + (size_t)rb * DD + (ch + 1) * 64;
            const __half* Wc = Wt + (size_t)cb * DD + (ch + 1) * 64;
#pragma unroll
            for (int i = 0; i < 4; i++) {
                int idx = tid + 256 * i;
                int row = idx >> 3, c = idx & 7;
                CP_ASYNC16(smbase + (uint32_t)((nb ? POFF_X1 : POFF_X0) + row * PSTR + c * 8) * 2,
                           Xc + (size_t)row * DD + c * 8);
                CP_ASYNC16(smbase + (uint32_t)((nb ? POFF_W1 : POFF_W0) + row * PSTR + c * 8) * 2,
                           Wc + (size_t)row * DD + c * 8);
            }
            CP_COMMIT();
            CP_WAIT1();
        } else {
            CP_WAIT0();
        }
        __syncthreads();

        const __half* sX = smh + (cur ? POFF_X1 : POFF_X0);
        const __half* sW = smh + (cur ? POFF_W1 : POFF_W0);

#pragma unroll
        for (int ko = 0; ko < 4; ko++) {
            const __half* x0 = sX + (wr * 32 + gid) * PSTR + 16 * ko + 2 * tig;
            uint32_t a00 = *(const uint32_t*)x0;
            uint32_t a01 = *(const uint32_t*)(x0 + 8 * PSTR);
            uint32_t a02 = *(const uint32_t*)(x0 + 8);
            uint32_t a03 = *(const uint32_t*)(x0 + 8 * PSTR + 8);
            uint32_t a10 = *(const uint32_t*)(x0 + 16 * PSTR);
            uint32_t a11 = *(const uint32_t*)(x0 + 24 * PSTR);
            uint32_t a12 = *(const uint32_t*)(x0 + 16 * PSTR + 8);
            uint32_t a13 = *(const uint32_t*)(x0 + 24 * PSTR + 8);
#pragma unroll
            for (int nt = 0; nt < 8; nt++) {
                const __half* wrow = sW + (wc * 64 + nt * 8 + gid) * PSTR + 16 * ko + 2 * tig;
                uint32_t b0 = *(const uint32_t*)wrow;
                uint32_t b1 = *(const uint32_t*)(wrow + 8);
                mma16(acc0[nt], a00, a01, a02, a03, b0, b1);
                mma16(acc1[nt], a10, a11, a12, a13, b0, b1);
            }
        }
        __syncthreads();
    }

    // epilogue
    const int r0 = rb + wr * 32 + gid;
    const int colbase = cb + wc * 64;
    if (z == 2) {
        // Transposed store for V: Vt[((b*8+h)*64+p)*MM + m]
        const int b_ = rb >> 12;
        const int h_ = colbase >> 6;
        __half* Vtb = Y + ((size_t)(b_ * HH + h_) * PP) * MM;
        const int m0 = r0 & (NN - 1);
#pragma unroll
        for (int nt = 0; nt < 8; nt++) {
            int p = nt * 8 + 2 * tig;          // head-dim index
            int col = colbase + p;
            float2 bv2 = *(const float2*)(bias + col);
            Vtb[(size_t)p * MM + m0]            = __float2half(acc0[nt][0] + bv2.x);
            Vtb[(size_t)(p + 1) * MM + m0]      = __float2half(acc0[nt][1] + bv2.y);
            Vtb[(size_t)p * MM + m0 + 8]        = __float2half(acc0[nt][2] + bv2.x);
            Vtb[(size_t)(p + 1) * MM + m0 + 8]  = __float2half(acc0[nt][3] + bv2.y);
            Vtb[(size_t)p * MM + m0 + 16]       = __float2half(acc1[nt][0] + bv2.x);
            Vtb[(size_t)(p + 1) * MM + m0 + 16] = __float2half(acc1[nt][1] + bv2.y);
            Vtb[(size_t)p * MM + m0 + 24]       = __float2half(acc1[nt][2] + bv2.x);
            Vtb[(size_t)(p + 1) * MM + m0 + 24] = __float2half(acc1[nt][3] + bv2.y);
        }
    } else {
#pragma unroll
        for (int nt = 0; nt < 8; nt++) {
            int col = colbase + nt * 8 + 2 * tig;
            float2 bv2 = *(const float2*)(bias + col);
            uint32_t o;
            o = packh2((acc0[nt][0] + bv2.x) * sc, (acc0[nt][1] + bv2.y) * sc);
            *(uint32_t*)(Y + (size_t)r0 * DD + col) = o;
            o = packh2((acc0[nt][2] + bv2.x) * sc, (acc0[nt][3] + bv2.y) * sc);
            *(uint32_t*)(Y + (size_t)(r0 + 8) * DD + col) = o;
            o = packh2((acc1[nt][0] + bv2.x) * sc, (acc1[nt][1] + bv2.y) * sc);
            *(uint32_t*)(Y + (size_t)(r0 + 16) * DD + col) = o;
            o = packh2((acc1[nt][2] + bv2.x) * sc, (acc1[nt][3] + bv2.y) * sc);
            *(uint32_t*)(Y + (size_t)(r0 + 24) * DD + col) = o;
        }
    }
}

// ================= Flash attention: fp16 m16n8k16, Vt d-major =====
// CTA = 128 thr (4 warps), 128 q rows (32/warp), KV tile 64 keys dbl-buffered.
// Scores pre-scaled by log2(e)/sqrt(P): base-2 softmax. Warp-uniform EXACT
// skip of acc/l rescale when no group's running max changed (corr == 1).
#define KT    64
#define NTIL  (MM / KT)
#define KSTRH 72

__shared__ __half sKh[2][KT * KSTRH];
__shared__ __half sVt[2][PP * KSTRH];   // [d][key], 64 x 72

// max over this thread's fragment components for one 16-row group + quad reduce
#define GRP_MAX(sarr, i0, i1, outmx) do {                                     \
    float _mx = fmaxf(sarr[0][i0], sarr[0][i1]);                              \
    _Pragma("unroll")                                                         \
    for (int _nt = 1; _nt < 8; _nt++)                                         \
        _mx = fmaxf(_mx, fmaxf(sarr[_nt][i0], sarr[_nt][i1]));                \
    _mx = fmaxf(_mx, __shfl_xor_sync(0xffffffffu, _mx, 1));                   \
    _mx = fmaxf(_mx, __shfl_xor_sync(0xffffffffu, _mx, 2));                   \
    outmx = _mx;                                                              \
} while (0)

// exp2 of shifted scores + row-sum + l update for one group
#define GRP_EXP(sarr, i0, i1, mvar, lvar) do {                                \
    float _sum = 0.0f;                                                        \
    _Pragma("unroll")                                                         \
    for (int _nt = 0; _nt < 8; _nt++) {                                       \
        sarr[_nt][i0] = exp2f(sarr[_nt][i0] - mvar);                          \
        sarr[_nt][i1] = exp2f(sarr[_nt][i1] - mvar);                          \
        _sum += sarr[_nt][i0] + sarr[_nt][i1];                                \
    }                                                                         \
    _sum += __shfl_xor_sync(0xffffffffu, _sum, 1);                            \
    _sum += __shfl_xor_sync(0xffffffffu, _sum, 2);                            \
    lvar += _sum;                                                             \
} while (0)

__global__ void __launch_bounds__(128, 2) attn_mma_kernel(
    const __half* __restrict__ Q, const __half* __restrict__ K,
    const __half* __restrict__ Vt, float* __restrict__ O)
{
    const int tid  = threadIdx.x;
    const int lane = tid & 31;
    const int w    = tid >> 5;
    const int gid  = lane >> 2;
    const int tig  = lane & 3;

    const int b  = blockIdx.z;
    const int h  = blockIdx.y;
    const int q0 = blockIdx.x * 128;

    const __half* Qb  = Q + ((size_t)(b * NN + q0 + w * 32)) * DD + h * PP;
    const __half* Kb  = K + ((size_t)b * MM) * DD + h * PP;
    const __half* Vtb = Vt + ((size_t)(b * HH + h) * PP) * MM;   // [p][m]

    const uint32_t kb0 = smem_u32(&sKh[0][0]);
    const uint32_t kb1 = smem_u32(&sKh[1][0]);
    const uint32_t vb0 = smem_u32(&sVt[0][0]);
    const uint32_t vb1 = smem_u32(&sVt[1][0]);

#pragma unroll
    for (int i = 0; i < 4; i++) {
        int idx = tid + 128 * i;
        int row = idx >> 3, c = idx & 7;
        CP_ASYNC16(kb0 + (uint32_t)(row * KSTRH + c * 8) * 2,
                   Kb + (size_t)row * DD + c * 8);
        CP_ASYNC16(vb0 + (uint32_t)(row * KSTRH + c * 8) * 2,
                   Vtb + (size_t)row * MM + c * 8);
    }
    CP_COMMIT();

    uint32_t qa0[4][4], qa1[4][4];
#pragma unroll
    for (int ko = 0; ko < 4; ko++) {
        int d0 = 16 * ko + 2 * tig;
        qa0[ko][0] = *(const uint32_t*)(Qb + (size_t)gid * DD + d0);
        qa0[ko][1] = *(const uint32_t*)(Qb + (size_t)(gid + 8) * DD + d0);
        qa0[ko][2] = *(const uint32_t*)(Qb + (size_t)gid * DD + d0 + 8);
        qa0[ko][3] = *(const uint32_t*)(Qb + (size_t)(gid + 8) * DD + d0 + 8);
        qa1[ko][0] = *(const uint32_t*)(Qb + (size_t)(gid + 16) * DD + d0);
        qa1[ko][1] = *(const uint32_t*)(Qb + (size_t)(gid + 24) * DD + d0);
        qa1[ko][2] = *(const uint32_t*)(Qb + (size_t)(gid + 16) * DD + d0 + 8);
        qa1[ko][3] = *(const uint32_t*)(Qb + (size_t)(gid + 24) * DD + d0 + 8);
    }

    float acc0[8][4], acc1[8][4];
#pragma unroll
    for (int nt = 0; nt < 8; nt++)
#pragma unroll
        for (int c = 0; c < 4; c++) { acc0[nt][c] = 0.0f; acc1[nt][c] = 0.0f; }
    float m00 = -CUDART_INF_F, m01 = -CUDART_INF_F;
    float m10 = -CUDART_INF_F, m11 = -CUDART_INF_F;
    float l00 = 0.0f, l01 = 0.0f, l10 = 0.0f, l11 = 0.0f;

    for (int t = 0; t < NTIL; t++) {
        int cur = t & 1;
        if (t + 1 < NTIL) {
            uint32_t kb = (t + 1) & 1 ? kb1 : kb0;
            uint32_t vb = (t + 1) & 1 ? vb1 : vb0;
            const __half* Ks  = Kb + (size_t)(t + 1) * KT * DD;
            const __half* Vts = Vtb + (t + 1) * KT;
#pragma unroll
            for (int i = 0; i < 4; i++) {
                int idx = tid + 128 * i;
                int row = idx >> 3, c = idx & 7;
                CP_ASYNC16(kb + (uint32_t)(row * KSTRH + c * 8) * 2,
                           Ks + (size_t)row * DD + c * 8);
                CP_ASYNC16(vb + (uint32_t)(row * KSTRH + c * 8) * 2,
                           Vts + (size_t)row * MM + c * 8);
            }
            CP_COMMIT();
            CP_WAIT1();
        } else {
            CP_WAIT0();
        }
        __syncthreads();

        const __half* sK = &sKh[cur][0];
        const __half* sV = &sVt[cur][0];

        // --- QK^T ---
        float s0[8][4], s1[8][4];
#pragma unroll
        for (int nt = 0; nt < 8; nt++) {
            s0[nt][0] = s0[nt][1] = s0[nt][2] = s0[nt][3] = 0.0f;
            s1[nt][0] = s1[nt][1] = s1[nt][2] = s1[nt][3] = 0.0f;
            const __half* krow = sK + (nt * 8 + gid) * KSTRH;
#pragma unroll
            for (int ko = 0; ko < 4; ko++) {
                uint32_t b0 = *(const uint32_t*)(krow + 16 * ko + 2 * tig);
                uint32_t b1 = *(const uint32_t*)(krow + 16 * ko + 2 * tig + 8);
                mma16(s0[nt], qa0[ko][0], qa0[ko][1], qa0[ko][2], qa0[ko][3], b0, b1);
                mma16(s1[nt], qa1[ko][0], qa1[ko][1], qa1[ko][2], qa1[ko][3], b0, b1);
            }
        }

        // --- online softmax (base 2), exact rescale-skip ---
        float mx0, mx1, mx2, mx3;
        GRP_MAX(s0, 0, 1, mx0);
        GRP_MAX(s0, 2, 3, mx1);
        GRP_MAX(s1, 0, 1, mx2);
        GRP_MAX(s1, 2, 3, mx3);
        float mn00 = fmaxf(m00, mx0), mn01 = fmaxf(m01, mx1);
        float mn10 = fmaxf(m10, mx2), mn11 = fmaxf(m11, mx3);
        bool chg = (mn00 > m00) | (mn01 > m01) | (mn10 > m10) | (mn11 > m11);
        if (__any_sync(0xffffffffu, chg)) {
            float c00 = exp2f(m00 - mn00), c01 = exp2f(m01 - mn01);
            float c10 = exp2f(m10 - mn10), c11 = exp2f(m11 - mn11);
            l00 *= c00; l01 *= c01; l10 *= c10; l11 *= c11;
#pragma unroll
            for (int nt = 0; nt < 8; nt++) {
                acc0[nt][0] *= c00; acc0[nt][1] *= c00;
                acc0[nt][2] *= c01; acc0[nt][3] *= c01;
                acc1[nt][0] *= c10; acc1[nt][1] *= c10;
                acc1[nt][2] *= c11; acc1[nt][3] *= c11;
            }
        }
        m00 = mn00; m01 = mn01; m10 = mn10; m11 = mn11;
        GRP_EXP(s0, 0, 1, m00, l00);
        GRP_EXP(s0, 2, 3, m01, l01);
        GRP_EXP(s1, 0, 1, m10, l10);
        GRP_EXP(s1, 2, 3, m11, l11);

        // --- PV: P from registers; V B-frags contiguous in d-major sVt ---
#pragma unroll
        for (int ko = 0; ko < 4; ko++) {
            uint32_t a0 = packh2(s0[2*ko][0],   s0[2*ko][1]);
            uint32_t a1 = packh2(s0[2*ko][2],   s0[2*ko][3]);
            uint32_t a2 = packh2(s0[2*ko+1][0], s0[2*ko+1][1]);
            uint32_t a3 = packh2(s0[2*ko+1][2], s0[2*ko+1][3]);
            uint32_t c0 = packh2(s1[2*ko][0],   s1[2*ko][1]);
            uint32_t c1 = packh2(s1[2*ko][2],   s1[2*ko][3]);
            uint32_t c2 = packh2(s1[2*ko+1][0], s1[2*ko+1][1]);
            uint32_t c3 = packh2(s1[2*ko+1][2], s1[2*ko+1][3]);
#pragma unroll
            for (int nt = 0; nt < 8; nt++) {
                const __half* vrow = sV + (nt * 8 + gid) * KSTRH + 16 * ko + 2 * tig;
                uint32_t b0 = *(const uint32_t*)vrow;
                uint32_t b1 = *(const uint32_t*)(vrow + 8);
                mma16(acc0[nt], a0, a1, a2, a3, b0, b1);
                mma16(acc1[nt], c0, c1, c2, c3, b0, b1);
            }
        }
        __syncthreads();
    }

    // --- normalize & store ---
    float i00 = 1.0f / l00, i01 = 1.0f / l01, i10 = 1.0f / l10, i11 = 1.0f / l11;
    float* Ob = O + ((size_t)(b * NN + q0 + w * 32)) * DD + h * PP;
#pragma unroll
    for (int nt = 0; nt < 8; nt++) {
        int col = nt * 8 + 2 * tig;
        *(float2*)(Ob + (size_t)gid * DD + col) =
            make_float2(acc0[nt][0] * i00, acc0[nt][1] * i00);
        *(float2*)(Ob + (size_t)(gid + 8) * DD + col) =
            make_float2(acc0[nt][2] * i01, acc0[nt][3] * i01);
        *(float2*)(Ob + (size_t)(gid + 16) * DD + col) =
            make_float2(acc1[nt][0] * i10, acc1[nt][1] * i10);
        *(float2*)(Ob + (size_t)(gid + 24) * DD + col) =
            make_float2(acc1[nt][2] * i11, acc1[nt][3] * i11);
    }
}

// ---------------- launch ----------------
extern "C" void kernel_launch(void* const* d_in, const int* in_sizes, int n_in,
                              void* d_out, int out_size)
{
    const float* queries = (const float*)d_in[0];
    const float* keys    = (const float*)d_in[1];
    const float* values  = (const float*)d_in[2];
    const float* Wq      = (const float*)d_in[3];
    const float* bq      = (const float*)d_in[4];
    const float* Wk      = (const float*)d_in[5];
    const float* bk      = (const float*)d_in[6];
    const float* Wv      = (const float*)d_in[7];
    const float* bv      = (const float*)d_in[8];
    float* out = (float*)d_out;

    __half *pq, *pk, *pvt, *pxq, *pxk, *pxv, *pwq, *pwk, *pwv;
    cudaGetSymbolAddress((void**)&pq,  g_q);
    cudaGetSymbolAddress((void**)&pk,  g_k);
    cudaGetSymbolAddress((void**)&pvt, g_vt);
    cudaGetSymbolAddress((void**)&pxq, g_xq);
    cudaGetSymbolAddress((void**)&pxk, g_xk);
    cudaGetSymbolAddress((void**)&pxv, g_xv);
    cudaGetSymbolAddress((void**)&pwq, g_wqt);
    cudaGetSymbolAddress((void**)&pwk, g_wkt);
    cudaGetSymbolAddress((void**)&pwv, g_wvt);

    // Convert inputs to fp16 (X elementwise; W transposed), fused launches.
    const int nX4 = (RR * DD) / 4;
    f2h3_kernel<<<dim3(1024, 1, 3), 256>>>(
        (const float4*)queries, (const float4*)keys, (const float4*)values,
        pxq, pxk, pxv, nX4);
    wt_h3_kernel<<<dim3(DD / 32, DD / 32, 3), dim3(32, 8)>>>(
        Wq, Wk, Wv, pwq, pwk, pwv);

    cudaFuncSetAttribute(proj_mma_kernel,
                         cudaFuncAttributeMaxDynamicSharedMemorySize, PROJ_SMEM_BYTES);
    dim3 pGrid(DD / 128, RR / 128, 3);   // (4, 64, 3)
    proj_mma_kernel<<<pGrid, 256, PROJ_SMEM_BYTES>>>(
        pxq, pxk, pxv, pwq, pwk, pwv, bq, bk, bv, pq, pk, pvt);

    dim3 aGrid(NN / 128, HH, BB);        // (32, 8, 2)
    attn_mma_kernel<<<aGrid, 128>>>(pq, pk, pvt, out);
}